// round 1
// baseline (speedup 1.0000x reference)
#include <cuda_runtime.h>
#include <cuda_bf16.h>

// ---------------------------------------------------------------------------
// ConvTransE scoring, algebraically reduced:
//   score[i] = e_t[i]^T (proj_w @ relu(conv(x_i)+b) + proj_b),  x_i = [h_e ; r_e]
// Only positions p<=511 of the conv output survive truncation; p<=510 windows
// touch only h_e (tiny values), p==511 additionally touches r_e[0].
// Channels whose bias dominates the conv bound are exactly linear (folded into
// an effective 512x512 matrix) or exactly zero. Remaining terms go through
// exact-ReLU correction columns of a single fused GEMM.
// ---------------------------------------------------------------------------

#define BATCH    2048
#define DIM      512
#define CH       32
#define LDB      16960          // >= 265*64, float4-aligned row stride of B
// column layout of B: [0,512) = folded linear matrix M (coef = h_e[i,j])
//                     512     = const column (proj_b + linear bias fold, coef=1)
//                     [513,545) = p==511 edge columns, all 32 channels (coef = exact relu)
//                     [545, 545+511*U) = uncertain-channel columns p in [0,511) (coef = exact relu)

__device__ __align__(16) float g_B[512 * LDB];     // built GEMM B matrix
__device__ __align__(16) float g_H[BATCH * DIM];   // gathered h_e rows
__device__ __align__(16) float g_A[BATCH * DIM];   // gathered e_t rows (GEMM A)
__device__ float        g_r0[BATCH];               // rel[r[i]][0]
__device__ unsigned int g_xmax_bits;               // max |h_e| over gathered rows
__device__ int          g_class[CH];               // 0=zero 1=linear 2=uncertain
__device__ int          g_unc[CH];                 // compact list of uncertain channels
__device__ int          g_uidx[CH];                // channel -> index in g_unc
__device__ int          g_N;                       // runtime #columns = 545 + 511*U

// ---------------------------------------------------------------- K0: init
__global__ void k0_init(float* __restrict__ out) {
    int id = blockIdx.x * blockDim.x + threadIdx.x;
    if (id < BATCH) out[id] = 0.0f;
    if (id == 0) g_xmax_bits = 0u;
}

// ------------------------------------------- K1: gather rows + max|h_e|
__global__ __launch_bounds__(128) void k1_gather(
    const int* __restrict__ h, const int* __restrict__ r, const int* __restrict__ t,
    const float* __restrict__ ent, const float* __restrict__ rel)
{
    int i = blockIdx.x;
    int tid = threadIdx.x;               // 128 threads, one float4 each
    const float4* hs = (const float4*)(ent + (size_t)h[i] * DIM);
    const float4* ts = (const float4*)(ent + (size_t)t[i] * DIM);
    float4 hv = hs[tid];
    float4 tv = ts[tid];
    ((float4*)g_H)[i * 128 + tid] = hv;
    ((float4*)g_A)[i * 128 + tid] = tv;
    float m = fmaxf(fmaxf(fabsf(hv.x), fabsf(hv.y)), fmaxf(fabsf(hv.z), fabsf(hv.w)));
    #pragma unroll
    for (int off = 16; off > 0; off >>= 1)
        m = fmaxf(m, __shfl_xor_sync(0xffffffffu, m, off));
    __shared__ float wm[4];
    if ((tid & 31) == 0) wm[tid >> 5] = m;
    __syncthreads();
    if (tid == 0) {
        float mm = fmaxf(fmaxf(wm[0], wm[1]), fmaxf(wm[2], wm[3]));
        atomicMax(&g_xmax_bits, __float_as_uint(mm));   // nonneg floats: bit order == value order
        g_r0[i] = rel[(size_t)r[i] * DIM];
    }
}

// ------------------------------------------- K2: per-channel classification
__global__ void k2_classify(const float* __restrict__ cw, const float* __restrict__ cb) {
    int c = threadIdx.x;                 // 32 threads
    float xmax = __uint_as_float(g_xmax_bits);
    float bound = (fabsf(cw[c * 3 + 0]) + fabsf(cw[c * 3 + 1]) + fabsf(cw[c * 3 + 2])) * xmax;
    float b = cb[c];
    int cls = (b >= bound) ? 1 : ((b <= -bound) ? 0 : 2);
    g_class[c] = cls;
    unsigned m = __ballot_sync(0xffffffffu, cls == 2);
    if (cls == 2) {
        int idx = __popc(m & ((1u << c) - 1u));
        g_unc[idx] = c;
        g_uidx[c] = idx;
    }
    if (c == 0) g_N = 545 + 511 * __popc(m);
}

// ------------------------------------------- K3: fold conv+proj_w into B
__global__ __launch_bounds__(256) void k3_build(
    const float* __restrict__ pw, const float* __restrict__ pb,
    const float* __restrict__ cw, const float* __restrict__ cb)
{
    int d = blockIdx.x;                  // 512 blocks, one per output dim d
    int t = threadIdx.x;                 // 256 threads
    __shared__ float seg[512];
    __shared__ float accM[512];
    __shared__ float red[256];
    accM[t] = 0.0f; accM[t + 256] = 0.0f;
    float cpart = 0.0f;
    const float* prow = pw + (size_t)d * (CH * DIM);
    size_t brow = (size_t)d * LDB;

    for (int c = 0; c < CH; c++) {
        seg[t]       = prow[c * DIM + t];
        seg[t + 256] = prow[c * DIM + t + 256];
        __syncthreads();
        int cls = g_class[c];
        if (t == 0) g_B[brow + 513 + c] = seg[511];          // edge column (p==511)
        if (cls == 1) {
            float w0 = cw[c * 3 + 0], w1 = cw[c * 3 + 1], w2 = cw[c * 3 + 2];
            #pragma unroll
            for (int n = t; n < 512; n += 256) {
                // x index n feeds conv position p = n+1-k (need 0 <= p <= 510)
                float s = 0.0f;
                if (n <= 509) s = w0 * seg[n + 1];
                if (n <= 510) s = fmaf(w1, seg[n], s);
                if (n >= 1)   s = fmaf(w2, seg[n - 1], s);
                accM[n] += s;
            }
            float ls = 0.0f;
            for (int p = t; p <= 510; p += 256) ls += seg[p];
            cpart = fmaf(cb[c], ls, cpart);                  // bias fold for const column
        } else if (cls == 2) {
            size_t base = brow + 545 + (size_t)g_uidx[c] * 511;
            for (int p = t; p < 511; p += 256) g_B[base + p] = seg[p];
        }
        __syncthreads();
    }
    g_B[brow + t]       = accM[t];
    g_B[brow + t + 256] = accM[t + 256];
    red[t] = cpart;
    __syncthreads();
    #pragma unroll
    for (int s = 128; s > 0; s >>= 1) {
        if (t < s) red[t] += red[t + s];
        __syncthreads();
    }
    if (t == 0) g_B[brow + 512] = red[0] + pb[d];            // const column
}

// ------------------------------------------- K4: fused GEMM + scoring
// u[i,n] = sum_d A[i,d]*B[d,n];  score[i] += sum_n u[i,n]*coef(i,n)
#define BM 128
#define BN 64
#define BK 16

__global__ __launch_bounds__(256) void k4_gemm(
    const float* __restrict__ cw, const float* __restrict__ cb,
    float* __restrict__ out)
{
    const int Ncols = g_N;
    const int n0 = blockIdx.x * BN;
    if (n0 >= Ncols) return;             // runtime-N early exit (worst-case grid)
    const int m0 = blockIdx.y * BM;

    __shared__ float As[BK][BM];
    __shared__ float Bs[BK][BN];

    int tid = threadIdx.x;
    int tx = tid & 15, ty = tid >> 4;
    float acc[8][4];
    #pragma unroll
    for (int i = 0; i < 8; i++)
        #pragma unroll
        for (int j = 0; j < 4; j++) acc[i][j] = 0.0f;

    int a_row = tid >> 2;                // 0..63
    int a_col = (tid & 3) << 2;          // 0,4,8,12
    int b_row = tid >> 4;                // 0..15
    int b_col = (tid & 15) << 2;         // 0..60

    for (int k0 = 0; k0 < DIM; k0 += BK) {
        #pragma unroll
        for (int r = 0; r < 2; r++) {
            float4 v = *(const float4*)&g_A[(size_t)(m0 + a_row + r * 64) * DIM + k0 + a_col];
            As[a_col + 0][a_row + r * 64] = v.x;
            As[a_col + 1][a_row + r * 64] = v.y;
            As[a_col + 2][a_row + r * 64] = v.z;
            As[a_col + 3][a_row + r * 64] = v.w;
        }
        float4 bv = *(const float4*)&g_B[(size_t)(k0 + b_row) * LDB + n0 + b_col];
        *(float4*)&Bs[b_row][b_col] = bv;
        __syncthreads();
        #pragma unroll
        for (int kk = 0; kk < BK; kk++) {
            float a0[8], bb[4];
            *(float4*)&a0[0] = *(const float4*)&As[kk][ty * 8];
            *(float4*)&a0[4] = *(const float4*)&As[kk][ty * 8 + 4];
            *(float4*)&bb[0] = *(const float4*)&Bs[kk][tx * 4];
            #pragma unroll
            for (int i = 0; i < 8; i++)
                #pragma unroll
                for (int j = 0; j < 4; j++) acc[i][j] = fmaf(a0[i], bb[j], acc[i][j]);
        }
        __syncthreads();
    }

    // epilogue: coef-weighted reduction over the 64 columns of this tile
    float rowsum[8];
    #pragma unroll
    for (int i = 0; i < 8; i++) rowsum[i] = 0.0f;

    #pragma unroll
    for (int j = 0; j < 4; j++) {
        int n = n0 + tx * 4 + j;
        if (n >= Ncols) continue;
        if (n < 512) {
            #pragma unroll
            for (int i = 0; i < 8; i++) {
                int row = m0 + ty * 8 + i;
                rowsum[i] = fmaf(acc[i][j], g_H[(size_t)row * DIM + n], rowsum[i]);
            }
        } else if (n == 512) {
            #pragma unroll
            for (int i = 0; i < 8; i++) rowsum[i] += acc[i][j];
        } else if (n < 545) {
            int c = n - 513;
            float w0 = cw[c * 3], w1 = cw[c * 3 + 1], w2 = cw[c * 3 + 2], b = cb[c];
            #pragma unroll
            for (int i = 0; i < 8; i++) {
                int row = m0 + ty * 8 + i;
                const float* Hr = &g_H[(size_t)row * DIM];
                float v = fmaf(w0, Hr[510], fmaf(w1, Hr[511], fmaf(w2, g_r0[row], b)));
                rowsum[i] = fmaf(acc[i][j], fmaxf(v, 0.0f), rowsum[i]);
            }
        } else {
            int q = n - 545;
            int ui = q / 511;
            int p = q - ui * 511;        // p in [0, 510]
            int c = g_unc[ui];
            float w0 = cw[c * 3], w1 = cw[c * 3 + 1], w2 = cw[c * 3 + 2], b = cb[c];
            #pragma unroll
            for (int i = 0; i < 8; i++) {
                int row = m0 + ty * 8 + i;
                const float* Hr = &g_H[(size_t)row * DIM];
                float xm1 = (p == 0) ? 0.0f : Hr[p - 1];
                float v = fmaf(w0, xm1, fmaf(w1, Hr[p], fmaf(w2, Hr[p + 1], b)));
                rowsum[i] = fmaf(acc[i][j], fmaxf(v, 0.0f), rowsum[i]);
            }
        }
    }

    // reduce over the 16 tx lanes (width-16 groups within each warp), then atomic
    #pragma unroll
    for (int i = 0; i < 8; i++) {
        float v = rowsum[i];
        #pragma unroll
        for (int off = 8; off > 0; off >>= 1)
            v += __shfl_down_sync(0xffffffffu, v, off, 16);
        if (tx == 0) atomicAdd(&out[m0 + ty * 8 + i], v);
    }
}

// ---------------------------------------------------------------------------
extern "C" void kernel_launch(void* const* d_in, const int* in_sizes, int n_in,
                              void* d_out, int out_size)
{
    const int*   h      = (const int*)  d_in[0];
    const int*   r      = (const int*)  d_in[1];
    const int*   t      = (const int*)  d_in[2];
    const float* ent    = (const float*)d_in[3];
    const float* rel    = (const float*)d_in[4];
    const float* conv_w = (const float*)d_in[5];
    const float* conv_b = (const float*)d_in[6];
    const float* proj_w = (const float*)d_in[7];
    const float* proj_b = (const float*)d_in[8];
    float* out = (float*)d_out;

    k0_init<<<8, 256>>>(out);
    k1_gather<<<BATCH, 128>>>(h, r, t, ent, rel);
    k2_classify<<<1, 32>>>(conv_w, conv_b);
    k3_build<<<512, 256>>>(proj_w, proj_b, conv_w, conv_b);
    // worst-case grid over columns (N known only on device); blocks past N exit
    k4_gemm<<<dim3(265, 16), 256>>>(conv_w, conv_b, out);
}

// round 4
// speedup vs baseline: 1.0529x; 1.0529x over previous
#include <cuda_runtime.h>
#include <cuda_bf16.h>

// ---------------------------------------------------------------------------
// ConvTransE scoring, algebraically reduced:
//   score[i] = e_t[i]^T (proj_w @ relu(conv(x_i)+b) + proj_b),  x_i = [h_e ; r_e]
// Channels whose bias dominates the conv bound are exactly linear (folded into
// an effective 512x512 matrix) or exactly zero; remaining terms go through
// exact-ReLU correction columns of a single fused GEMM.
// ---------------------------------------------------------------------------

#define BATCH    2048
#define DIM      512
#define CH       32
#define LDB      16960          // >= 265*64, float4-aligned row stride of B

__device__ __align__(16) float g_B[512 * LDB];     // built GEMM B matrix
__device__ __align__(16) float g_H[BATCH * DIM];   // gathered h_e rows
__device__ __align__(16) float g_A[BATCH * DIM];   // gathered e_t rows (GEMM A)
__device__ float        g_r0[BATCH];               // rel[r[i]][0]
__device__ unsigned int g_xmax_bits;               // max |h_e| over gathered rows
__device__ int          g_class[CH];               // 0=zero 1=linear 2=uncertain
__device__ int          g_unc[CH];                 // compact list of uncertain channels
__device__ int          g_uidx[CH];                // channel -> index in g_unc
__device__ int          g_N;                       // runtime #columns = 545 + 511*U

// ---------------------------------------------------------------- K0: init
__global__ void k0_init(float* __restrict__ out) {
    int id = blockIdx.x * blockDim.x + threadIdx.x;
    if (id < BATCH) out[id] = 0.0f;
    if (id == 0) g_xmax_bits = 0u;
}

// ------------------------------------------- K1: gather rows + max|h_e|
__global__ __launch_bounds__(128) void k1_gather(
    const int* __restrict__ h, const int* __restrict__ r, const int* __restrict__ t,
    const float* __restrict__ ent, const float* __restrict__ rel)
{
    int i = blockIdx.x;
    int tid = threadIdx.x;               // 128 threads, one float4 each
    const float4* hs = (const float4*)(ent + (size_t)h[i] * DIM);
    const float4* ts = (const float4*)(ent + (size_t)t[i] * DIM);
    float4 hv = hs[tid];
    float4 tv = ts[tid];
    ((float4*)g_H)[i * 128 + tid] = hv;
    ((float4*)g_A)[i * 128 + tid] = tv;
    float m = fmaxf(fmaxf(fabsf(hv.x), fabsf(hv.y)), fmaxf(fabsf(hv.z), fabsf(hv.w)));
    #pragma unroll
    for (int off = 16; off > 0; off >>= 1)
        m = fmaxf(m, __shfl_xor_sync(0xffffffffu, m, off));
    __shared__ float wm[4];
    if ((tid & 31) == 0) wm[tid >> 5] = m;
    __syncthreads();
    if (tid == 0) {
        float mm = fmaxf(fmaxf(wm[0], wm[1]), fmaxf(wm[2], wm[3]));
        atomicMax(&g_xmax_bits, __float_as_uint(mm));   // nonneg floats: bit order == value order
        g_r0[i] = rel[(size_t)r[i] * DIM];
    }
}

// ------------------------------------------- K2: per-channel classification
__global__ void k2_classify(const float* __restrict__ cw, const float* __restrict__ cb) {
    int c = threadIdx.x;                 // 32 threads (one full warp)
    float xmax = __uint_as_float(g_xmax_bits);
    float bound = (fabsf(cw[c * 3 + 0]) + fabsf(cw[c * 3 + 1]) + fabsf(cw[c * 3 + 2])) * xmax;
    float b = cb[c];
    int cls = (b >= bound) ? 1 : ((b <= -bound) ? 0 : 2);
    g_class[c] = cls;
    unsigned m = __ballot_sync(0xffffffffu, cls == 2);
    if (cls == 2) {
        int idx = __popc(m & ((1u << c) - 1u));
        g_unc[idx] = c;
        g_uidx[c] = idx;
    }
    if (c == 0) g_N = 545 + 511 * __popc(m);
}

// ------------------------------------------- K3: fold conv+proj_w into B
// Bulk-load 32KB halves of the proj_w row into smem (MLP 16), then fold all
// 16 channels of that half with register accumulators. One sync per half.
__global__ __launch_bounds__(256) void k3_build(
    const float* __restrict__ pw, const float* __restrict__ pb,
    const float* __restrict__ cw, const float* __restrict__ cb)
{
    int d = blockIdx.x;                  // 512 blocks, one per output dim d
    int t = threadIdx.x;                 // 256 threads
    __shared__ __align__(16) float seg[16 * 512];   // 32KB: 16 channels
    __shared__ float red[256];
    float acc0 = 0.0f, acc1 = 0.0f;      // folded M row entries for n=t, n=t+256
    float cpart = 0.0f;
    const float* prow = pw + (size_t)d * (CH * DIM);
    size_t brow = (size_t)d * LDB;
    const int n1 = t + 256;

    for (int half = 0; half < 2; half++) {
        const float4* src = (const float4*)(prow + half * 16 * 512);
        #pragma unroll
        for (int j = 0; j < 8; j++)
            ((float4*)seg)[t + j * 256] = src[t + j * 256];
        __syncthreads();

        #pragma unroll 1
        for (int cc = 0; cc < 16; cc++) {
            int c = half * 16 + cc;
            const float* s = seg + cc * 512;
            int cls = g_class[c];
            if (t == 0) g_B[brow + 513 + c] = s[511];        // edge column (p==511)
            if (cls == 1) {
                float w0 = cw[c * 3 + 0], w1 = cw[c * 3 + 1], w2 = cw[c * 3 + 2];
                float bc = cb[c];
                // n = t (0..255): bounds n<=509, n<=510 always hold; n>=1 guards s[n-1]
                {
                    float s0  = s[t];
                    float sp1 = s[t + 1];
                    float v = fmaf(w0, sp1, w1 * s0);
                    if (t >= 1) v = fmaf(w2, s[t - 1], v);
                    acc0 += v;
                    cpart = fmaf(bc, s0, cpart);             // p=t <= 510 always
                }
                // n = t+256 (256..511)
                {
                    float v = w2 * s[n1 - 1];
                    if (n1 <= 510) v = fmaf(w1, s[n1], v);
                    if (n1 <= 509) v = fmaf(w0, s[n1 + 1], v);
                    acc1 += v;
                    if (n1 <= 510) cpart = fmaf(bc, s[n1], cpart);
                }
            } else if (cls == 2) {
                size_t base = brow + 545 + (size_t)g_uidx[c] * 511;
                g_B[base + t] = s[t];
                if (n1 < 511) g_B[base + n1] = s[n1];
            }
        }
        __syncthreads();
    }
    g_B[brow + t]   = acc0;
    g_B[brow + n1]  = acc1;
    red[t] = cpart;
    __syncthreads();
    #pragma unroll
    for (int sfd = 128; sfd > 0; sfd >>= 1) {
        if (t < sfd) red[t] += red[t + sfd];
        __syncthreads();
    }
    if (t == 0) g_B[brow + 512] = red[0] + pb[d];            // const column
}

// ------------------------------------------- K4: fused GEMM + scoring
// u[i,n] = sum_d A[i,d]*B[d,n];  score[i] += sum_n u[i,n]*coef(i,n)
#define BM 128
#define BN 64
#define BK 16

__global__ __launch_bounds__(256) void k4_gemm(
    const float* __restrict__ cw, const float* __restrict__ cb,
    float* __restrict__ out)
{
    const int Ncols = g_N;
    const int n0 = blockIdx.x * BN;
    if (n0 >= Ncols) return;             // runtime-N early exit (worst-case grid)
    const int m0 = blockIdx.y * BM;

    __shared__ float As[BK][BM];
    __shared__ float Bs[BK][BN];

    int tid = threadIdx.x;
    int tx = tid & 15, ty = tid >> 4;
    float acc[8][4];
    #pragma unroll
    for (int i = 0; i < 8; i++)
        #pragma unroll
        for (int j = 0; j < 4; j++) acc[i][j] = 0.0f;

    int a_row = tid >> 2;                // 0..63
    int a_col = (tid & 3) << 2;          // 0,4,8,12
    int b_row = tid >> 4;                // 0..15
    int b_col = (tid & 15) << 2;         // 0..60

    for (int k0 = 0; k0 < DIM; k0 += BK) {
        #pragma unroll
        for (int r = 0; r < 2; r++) {
            float4 v = *(const float4*)&g_A[(size_t)(m0 + a_row + r * 64) * DIM + k0 + a_col];
            As[a_col + 0][a_row + r * 64] = v.x;
            As[a_col + 1][a_row + r * 64] = v.y;
            As[a_col + 2][a_row + r * 64] = v.z;
            As[a_col + 3][a_row + r * 64] = v.w;
        }
        float4 bv = *(const float4*)&g_B[(size_t)(k0 + b_row) * LDB + n0 + b_col];
        *(float4*)&Bs[b_row][b_col] = bv;
        __syncthreads();
        #pragma unroll
        for (int kk = 0; kk < BK; kk++) {
            float a0[8], bb[4];
            *(float4*)&a0[0] = *(const float4*)&As[kk][ty * 8];
            *(float4*)&a0[4] = *(const float4*)&As[kk][ty * 8 + 4];
            *(float4*)&bb[0] = *(const float4*)&Bs[kk][tx * 4];
            #pragma unroll
            for (int i = 0; i < 8; i++)
                #pragma unroll
                for (int j = 0; j < 4; j++) acc[i][j] = fmaf(a0[i], bb[j], acc[i][j]);
        }
        __syncthreads();
    }

    // epilogue: coef-weighted reduction over the 64 columns of this tile
    float rowsum[8];
    #pragma unroll
    for (int i = 0; i < 8; i++) rowsum[i] = 0.0f;

    #pragma unroll
    for (int j = 0; j < 4; j++) {
        int n = n0 + tx * 4 + j;
        if (n >= Ncols) continue;
        if (n < 512) {
            #pragma unroll
            for (int i = 0; i < 8; i++) {
                int row = m0 + ty * 8 + i;
                rowsum[i] = fmaf(acc[i][j], g_H[(size_t)row * DIM + n], rowsum[i]);
            }
        } else if (n == 512) {
            #pragma unroll
            for (int i = 0; i < 8; i++) rowsum[i] += acc[i][j];
        } else if (n < 545) {
            int c = n - 513;
            float w0 = cw[c * 3], w1 = cw[c * 3 + 1], w2 = cw[c * 3 + 2], b = cb[c];
            #pragma unroll
            for (int i = 0; i < 8; i++) {
                int row = m0 + ty * 8 + i;
                const float* Hr = &g_H[(size_t)row * DIM];
                float v = fmaf(w0, Hr[510], fmaf(w1, Hr[511], fmaf(w2, g_r0[row], b)));
                rowsum[i] = fmaf(acc[i][j], fmaxf(v, 0.0f), rowsum[i]);
            }
        } else {
            int q = n - 545;
            int ui = q / 511;
            int p = q - ui * 511;        // p in [0, 510]
            int c = g_unc[ui];
            float w0 = cw[c * 3], w1 = cw[c * 3 + 1], w2 = cw[c * 3 + 2], b = cb[c];
            #pragma unroll
            for (int i = 0; i < 8; i++) {
                int row = m0 + ty * 8 + i;
                const float* Hr = &g_H[(size_t)row * DIM];
                float xm1 = (p == 0) ? 0.0f : Hr[p - 1];
                float v = fmaf(w0, xm1, fmaf(w1, Hr[p], fmaf(w2, Hr[p + 1], b)));
                rowsum[i] = fmaf(acc[i][j], fmaxf(v, 0.0f), rowsum[i]);
            }
        }
    }

    // reduce over the 16 tx lanes (width-16 groups within each warp), then atomic
    #pragma unroll
    for (int i = 0; i < 8; i++) {
        float v = rowsum[i];
        #pragma unroll
        for (int off = 8; off > 0; off >>= 1)
            v += __shfl_down_sync(0xffffffffu, v, off, 16);
        if (tx == 0) atomicAdd(&out[m0 + ty * 8 + i], v);
    }
}

// ---------------------------------------------------------------------------
extern "C" void kernel_launch(void* const* d_in, const int* in_sizes, int n_in,
                              void* d_out, int out_size)
{
    const int*   h      = (const int*)  d_in[0];
    const int*   r      = (const int*)  d_in[1];
    const int*   t      = (const int*)  d_in[2];
    const float* ent    = (const float*)d_in[3];
    const float* rel    = (const float*)d_in[4];
    const float* conv_w = (const float*)d_in[5];
    const float* conv_b = (const float*)d_in[6];
    const float* proj_w = (const float*)d_in[7];
    const float* proj_b = (const float*)d_in[8];
    float* out = (float*)d_out;

    k0_init<<<8, 256>>>(out);
    k1_gather<<<BATCH, 128>>>(h, r, t, ent, rel);
    k2_classify<<<1, 32>>>(conv_w, conv_b);
    k3_build<<<512, 256>>>(proj_w, proj_b, conv_w, conv_b);
    // worst-case grid over columns (N known only on device); blocks past N exit
    k4_gemm<<<dim3(265, 16), 256>>>(conv_w, conv_b, out);
}

// round 6
// speedup vs baseline: 1.3884x; 1.3187x over previous
#include <cuda_runtime.h>
#include <cuda_bf16.h>

// ---------------------------------------------------------------------------
// ConvTransE scoring, algebraically reduced:
//   score[i] = e_t[i]^T (proj_w @ relu(conv(x_i)+b) + proj_b),  x_i = [h_e ; r_e]
// Linear/zero channels folded into an effective 512x512 matrix; the few
// "uncertain" channels + the p==511 edge go through exact-ReLU correction
// columns of one fused GEMM. GEMM runs on tensor cores via hi/lo bf16 split
// (3x mma.sync m16n8k16, error ~2^-17), fp32 accumulate, fused scoring epilogue.
// ---------------------------------------------------------------------------

#define BATCH    2048
#define DIM      512
#define CH       32
#define LDB      16960          // >= 265*64, float4-aligned row stride of B
#define NMAXPAD  16960

__device__ __align__(16) float g_B[512 * LDB];       // built GEMM B matrix (fp32)
__device__ __align__(16) float g_H[BATCH * DIM];     // gathered h_e rows (fp32, coefs)
__device__ __align__(16) __nv_bfloat16 g_Ah[BATCH * DIM];   // A hi
__device__ __align__(16) __nv_bfloat16 g_Al[BATCH * DIM];   // A lo
__device__ __align__(16) __nv_bfloat16 g_Bth[NMAXPAD * DIM]; // B^T hi  [n][k]
__device__ __align__(16) __nv_bfloat16 g_Btl[NMAXPAD * DIM]; // B^T lo  [n][k]
__device__ float        g_r0[BATCH];               // rel[r[i]][0]
__device__ unsigned int g_xmax_bits;               // max |h_e| over gathered rows
__device__ int          g_class[CH];               // 0=zero 1=linear 2=uncertain
__device__ int          g_unc[CH];                 // compact list of uncertain channels
__device__ int          g_uidx[CH];                // channel -> index in g_unc
__device__ int          g_N;                       // runtime #columns = 545 + 511*U

#define MMA_BF16(C, A, B) \
    asm volatile("mma.sync.aligned.m16n8k16.row.col.f32.bf16.bf16.f32 " \
        "{%0,%1,%2,%3},{%4,%5,%6,%7},{%8,%9},{%0,%1,%2,%3};" \
        : "+f"(C[0]), "+f"(C[1]), "+f"(C[2]), "+f"(C[3]) \
        : "r"(A[0]), "r"(A[1]), "r"(A[2]), "r"(A[3]), "r"(B[0]), "r"(B[1]))

// -------------------- K0: init (zero scores + B's atomic-merge region) ------
__global__ __launch_bounds__(256) void k0_init(float* __restrict__ out) {
    int id = blockIdx.x * blockDim.x + threadIdx.x;
    if (id < BATCH) out[id] = 0.0f;
    if (id == 0) g_xmax_bits = 0u;
    const int total = 512 * 513;
    if (id < total) {
        int d = id / 513;
        int n = id - d * 513;
        g_B[(size_t)d * LDB + n] = 0.0f;
    }
}

// ------------------- K1: gather rows + max|h_e| + A hi/lo split -------------
__global__ __launch_bounds__(128) void k1_gather(
    const int* __restrict__ h, const int* __restrict__ r, const int* __restrict__ t,
    const float* __restrict__ ent, const float* __restrict__ rel)
{
    int i = blockIdx.x;
    int tid = threadIdx.x;               // 128 threads, one float4 each
    const float4* hs = (const float4*)(ent + (size_t)h[i] * DIM);
    const float4* ts = (const float4*)(ent + (size_t)t[i] * DIM);
    float4 hv = hs[tid];
    float4 tv = ts[tid];
    ((float4*)g_H)[i * 128 + tid] = hv;
    // hi/lo bf16 split of the e_t row (GEMM A)
    {
        float v[4] = {tv.x, tv.y, tv.z, tv.w};
        size_t base = (size_t)i * DIM + tid * 4;
        #pragma unroll
        for (int j = 0; j < 4; j++) {
            __nv_bfloat16 hi = __float2bfloat16(v[j]);
            __nv_bfloat16 lo = __float2bfloat16(v[j] - __bfloat162float(hi));
            g_Ah[base + j] = hi;
            g_Al[base + j] = lo;
        }
    }
    float m = fmaxf(fmaxf(fabsf(hv.x), fabsf(hv.y)), fmaxf(fabsf(hv.z), fabsf(hv.w)));
    #pragma unroll
    for (int off = 16; off > 0; off >>= 1)
        m = fmaxf(m, __shfl_xor_sync(0xffffffffu, m, off));
    __shared__ float wm[4];
    if ((tid & 31) == 0) wm[tid >> 5] = m;
    __syncthreads();
    if (tid == 0) {
        float mm = fmaxf(fmaxf(wm[0], wm[1]), fmaxf(wm[2], wm[3]));
        atomicMax(&g_xmax_bits, __float_as_uint(mm));   // nonneg floats: bit order == value order
        g_r0[i] = rel[(size_t)r[i] * DIM];
    }
}

// ------------------------------------------- K2: per-channel classification
__global__ void k2_classify(const float* __restrict__ cw, const float* __restrict__ cb) {
    int c = threadIdx.x;                 // 32 threads (one full warp)
    float xmax = __uint_as_float(g_xmax_bits);
    float bound = (fabsf(cw[c * 3 + 0]) + fabsf(cw[c * 3 + 1]) + fabsf(cw[c * 3 + 2])) * xmax;
    float b = cb[c];
    int cls = (b >= bound) ? 1 : ((b <= -bound) ? 0 : 2);
    g_class[c] = cls;
    unsigned m = __ballot_sync(0xffffffffu, cls == 2);
    if (cls == 2) {
        int idx = __popc(m & ((1u << c) - 1u));
        g_unc[idx] = c;
        g_uidx[c] = idx;
    }
    if (c == 0) g_N = 545 + 511 * __popc(m);
}

// ------------------------------------------- K3: fold conv+proj_w into B
// One block per (d, half): bulk-load a 32KB half of proj_w row d (16 channels,
// MLP 16), fold, atomicAdd partials into B's linear/const columns.
__global__ __launch_bounds__(256) void k3_build(
    const float* __restrict__ pw, const float* __restrict__ pb,
    const float* __restrict__ cw, const float* __restrict__ cb)
{
    int bx = blockIdx.x;                 // 1024 blocks
    int d = bx >> 1;
    int half = bx & 1;
    int t = threadIdx.x;                 // 256 threads
    __shared__ __align__(16) float seg[16 * 512];   // 32KB: 16 channels
    __shared__ float red[256];
    float acc0 = 0.0f, acc1 = 0.0f;
    float cpart = 0.0f;
    const float* prow = pw + (size_t)d * (CH * DIM) + half * 16 * 512;
    size_t brow = (size_t)d * LDB;
    const int n1 = t + 256;

    const float4* src = (const float4*)prow;
    #pragma unroll
    for (int j = 0; j < 8; j++)
        ((float4*)seg)[t + j * 256] = src[t + j * 256];
    __syncthreads();

    #pragma unroll 1
    for (int cc = 0; cc < 16; cc++) {
        int c = half * 16 + cc;
        const float* s = seg + cc * 512;
        int cls = g_class[c];
        if (t == 0) g_B[brow + 513 + c] = s[511];        // edge column (p==511)
        if (cls == 1) {
            float w0 = cw[c * 3 + 0], w1 = cw[c * 3 + 1], w2 = cw[c * 3 + 2];
            float bc = cb[c];
            {
                float s0  = s[t];
                float sp1 = s[t + 1];
                float v = fmaf(w0, sp1, w1 * s0);
                if (t >= 1) v = fmaf(w2, s[t - 1], v);
                acc0 += v;
                cpart = fmaf(bc, s0, cpart);
            }
            {
                float v = w2 * s[n1 - 1];
                if (n1 <= 510) v = fmaf(w1, s[n1], v);
                if (n1 <= 509) v = fmaf(w0, s[n1 + 1], v);
                acc1 += v;
                if (n1 <= 510) cpart = fmaf(bc, s[n1], cpart);
            }
        } else if (cls == 2) {
            size_t base = brow + 545 + (size_t)g_uidx[c] * 511;
            g_B[base + t] = s[t];
            if (n1 < 511) g_B[base + n1] = s[n1];
        }
    }
    atomicAdd(&g_B[brow + t],  acc0);
    atomicAdd(&g_B[brow + n1], acc1);
    red[t] = cpart;
    __syncthreads();
    #pragma unroll
    for (int sfd = 128; sfd > 0; sfd >>= 1) {
        if (t < sfd) red[t] += red[t + sfd];
        __syncthreads();
    }
    if (t == 0) {
        float v = red[0] + (half == 0 ? pb[d] : 0.0f);
        atomicAdd(&g_B[brow + 512], v);                  // const column
    }
}

// -------------------- K3.5: transpose + hi/lo split B -> Bt[n][k] -----------
__global__ __launch_bounds__(256) void k35_convertB() {
    const int Ncols = g_N;
    int n0 = blockIdx.y * 32;
    if (n0 >= Ncols) return;
    int k0 = blockIdx.x * 32;
    __shared__ float tile[32][33];
    int tx = threadIdx.x & 31, ty = threadIdx.x >> 5;   // ty 0..7
    #pragma unroll
    for (int rr = 0; rr < 4; rr++) {
        int kk = ty + rr * 8;
        tile[kk][tx] = g_B[(size_t)(k0 + kk) * LDB + n0 + tx];
    }
    __syncthreads();
    #pragma unroll
    for (int rr = 0; rr < 4; rr++) {
        int nn = ty + rr * 8;
        float v = tile[tx][nn];
        __nv_bfloat16 hv = __float2bfloat16(v);
        float lv = v - __bfloat162float(hv);
        g_Bth[(size_t)(n0 + nn) * DIM + k0 + tx] = hv;
        g_Btl[(size_t)(n0 + nn) * DIM + k0 + tx] = __float2bfloat16(lv);
    }
}

// -------------------- coef(row, col) for the scoring epilogue ---------------
__device__ __forceinline__ float coef_fn(int row, int n, int Ncols,
                                         const float* __restrict__ cw,
                                         const float* __restrict__ cb)
{
    if (n >= Ncols) return 0.0f;
    if (n < 512)  return g_H[(size_t)row * DIM + n];
    if (n == 512) return 1.0f;
    const float* Hr = &g_H[(size_t)row * DIM];
    if (n < 545) {
        int c = n - 513;
        float v = fmaf(cw[c * 3], Hr[510],
                  fmaf(cw[c * 3 + 1], Hr[511],
                  fmaf(cw[c * 3 + 2], g_r0[row], cb[c])));
        return fmaxf(v, 0.0f);
    }
    int q = n - 545;
    int ui = q / 511;
    int p = q - ui * 511;                // p in [0, 510]
    int c = g_unc[ui];
    float xm1 = (p == 0) ? 0.0f : Hr[p - 1];
    float v = fmaf(cw[c * 3], xm1,
              fmaf(cw[c * 3 + 1], Hr[p],
              fmaf(cw[c * 3 + 2], Hr[p + 1], cb[c])));
    return fmaxf(v, 0.0f);
}

// -------------------- K4: tensor-core GEMM + fused scoring ------------------
// Tile 128(m) x 64(n), k-step 16. 8 warps: wm = warp>>2 (m 64-offset),
// wn = warp&3 (n 16-offset). Per warp: 4 m16 subtiles x 2 n8 subtiles.
// 3 mmas per subtile pair (hi*hi + hi*lo + lo*hi).
__global__ __launch_bounds__(256) void k4_gemm(
    const float* __restrict__ cw, const float* __restrict__ cb,
    float* __restrict__ out)
{
    const int Ncols = g_N;
    const int n0 = blockIdx.x * 64;
    if (n0 >= Ncols) return;
    const int m0 = blockIdx.y * 128;

    __shared__ __align__(16) __nv_bfloat16 Ash[128][16];
    __shared__ __align__(16) __nv_bfloat16 Asl[128][16];
    __shared__ __align__(16) __nv_bfloat16 Bsh[64][16];
    __shared__ __align__(16) __nv_bfloat16 Bsl[64][16];

    const int tid  = threadIdx.x;
    const int lane = tid & 31;
    const int warp = tid >> 5;
    const int g = lane >> 2;             // 0..7
    const int q = lane & 3;              // 0..3
    const int wm = warp >> 2;            // 0..1
    const int wn = warp & 3;             // 0..3

    float c_[4][2][4];
    #pragma unroll
    for (int s = 0; s < 4; s++)
        #pragma unroll
        for (int u = 0; u < 2; u++)
            #pragma unroll
            for (int e = 0; e < 4; e++) c_[s][u][e] = 0.0f;

    const int arow = tid >> 1;           // 0..127
    const int ahalf = (tid & 1) * 8;
    const int brow = (tid & 127) >> 1;   // 0..63
    const int bhalf = (tid & 1) * 8;

    for (int k0 = 0; k0 < DIM; k0 += 16) {
        __syncthreads();
        *(uint4*)&Ash[arow][ahalf] = *(const uint4*)&g_Ah[(size_t)(m0 + arow) * DIM + k0 + ahalf];
        *(uint4*)&Asl[arow][ahalf] = *(const uint4*)&g_Al[(size_t)(m0 + arow) * DIM + k0 + ahalf];
        if (tid < 128) {
            *(uint4*)&Bsh[brow][bhalf] = *(const uint4*)&g_Bth[(size_t)(n0 + brow) * DIM + k0 + bhalf];
            *(uint4*)&Bsl[brow][bhalf] = *(const uint4*)&g_Btl[(size_t)(n0 + brow) * DIM + k0 + bhalf];
        }
        __syncthreads();

        unsigned afh[4][4], afl[4][4], bfh[2][2], bfl[2][2];
        #pragma unroll
        for (int s = 0; s < 4; s++) {
            int ms = wm * 64 + s * 16 + g;
            afh[s][0] = *(const unsigned*)&Ash[ms][2 * q];
            afh[s][1] = *(const unsigned*)&Ash[ms + 8][2 * q];
            afh[s][2] = *(const unsigned*)&Ash[ms][2 * q + 8];
            afh[s][3] = *(const unsigned*)&Ash[ms + 8][2 * q + 8];
            afl[s][0] = *(const unsigned*)&Asl[ms][2 * q];
            afl[s][1] = *(const unsigned*)&Asl[ms + 8][2 * q];
            afl[s][2] = *(const unsigned*)&Asl[ms][2 * q + 8];
            afl[s][3] = *(const unsigned*)&Asl[ms + 8][2 * q + 8];
        }
        #pragma unroll
        for (int u = 0; u < 2; u++) {
            int nb = wn * 16 + u * 8 + g;
            bfh[u][0] = *(const unsigned*)&Bsh[nb][2 * q];
            bfh[u][1] = *(const unsigned*)&Bsh[nb][2 * q + 8];
            bfl[u][0] = *(const unsigned*)&Bsl[nb][2 * q];
            bfl[u][1] = *(const unsigned*)&Bsl[nb][2 * q + 8];
        }
        #pragma unroll
        for (int s = 0; s < 4; s++)
            #pragma unroll
            for (int u = 0; u < 2; u++) {
                MMA_BF16(c_[s][u], afh[s], bfh[u]);
                MMA_BF16(c_[s][u], afh[s], bfl[u]);
                MMA_BF16(c_[s][u], afl[s], bfh[u]);
            }
    }

    // epilogue: coef-weighted reduction, then width-4 shfl + atomicAdd
    #pragma unroll
    for (int s = 0; s < 4; s++) {
        int row0 = m0 + wm * 64 + s * 16 + g;
        int row1 = row0 + 8;
        float rs0 = 0.0f, rs1 = 0.0f;
        #pragma unroll
        for (int u = 0; u < 2; u++) {
            int n = n0 + wn * 16 + u * 8 + 2 * q;
            float cf00 = coef_fn(row0, n,     Ncols, cw, cb);
            float cf01 = coef_fn(row0, n + 1, Ncols, cw, cb);
            float cf10 = coef_fn(row1, n,     Ncols, cw, cb);
            float cf11 = coef_fn(row1, n + 1, Ncols, cw, cb);
            rs0 = fmaf(c_[s][u][0], cf00, fmaf(c_[s][u][1], cf01, rs0));
            rs1 = fmaf(c_[s][u][2], cf10, fmaf(c_[s][u][3], cf11, rs1));
        }
        rs0 += __shfl_down_sync(0xffffffffu, rs0, 2, 4);
        rs0 += __shfl_down_sync(0xffffffffu, rs0, 1, 4);
        rs1 += __shfl_down_sync(0xffffffffu, rs1, 2, 4);
        rs1 += __shfl_down_sync(0xffffffffu, rs1, 1, 4);
        if (q == 0) {
            atomicAdd(&out[row0], rs0);
            atomicAdd(&out[row1], rs1);
        }
    }
}

// ---------------------------------------------------------------------------
extern "C" void kernel_launch(void* const* d_in, const int* in_sizes, int n_in,
                              void* d_out, int out_size)
{
    const int*   h      = (const int*)  d_in[0];
    const int*   r      = (const int*)  d_in[1];
    const int*   t      = (const int*)  d_in[2];
    const float* ent    = (const float*)d_in[3];
    const float* rel    = (const float*)d_in[4];
    const float* conv_w = (const float*)d_in[5];
    const float* conv_b = (const float*)d_in[6];
    const float* proj_w = (const float*)d_in[7];
    const float* proj_b = (const float*)d_in[8];
    float* out = (float*)d_out;

    k0_init<<<1032, 256>>>(out);
    k1_gather<<<BATCH, 128>>>(h, r, t, ent, rel);
    k2_classify<<<1, 32>>>(conv_w, conv_b);
    k3_build<<<1024, 256>>>(proj_w, proj_b, conv_w, conv_b);
    k35_convertB<<<dim3(16, 530), 256>>>();
    // worst-case grid over columns (N known only on device); blocks past N exit
    k4_gemm<<<dim3(265, 16), 256>>>(conv_w, conv_b, out);
}

// round 8
// speedup vs baseline: 1.7275x; 1.2442x over previous
#include <cuda_runtime.h>
#include <cuda_bf16.h>

// ---------------------------------------------------------------------------
// ConvTransE scoring, algebraically reduced:
//   score[i] = e_t[i]^T (proj_w @ relu(conv(x_i)+b) + proj_b),  x_i = [h_e ; r_e]
// Linear/zero channels folded into an effective 512x512 matrix; the few
// "uncertain" channels + the p==511 edge go through exact-ReLU correction
// columns of one fused GEMM. Tensor cores via hi/lo bf16 split (3x mma.sync
// m16n8k16), ldmatrix fragments, 2-stage cp.async pipeline in STATIC smem.
// ---------------------------------------------------------------------------

#define BATCH    2048
#define DIM      512
#define CH       32
#define LDB      16960          // >= 265*64, float4-aligned row stride of B
#define NMAXPAD  16960

__device__ __align__(16) float g_B[512 * LDB];       // built GEMM B matrix (fp32)
__device__ __align__(16) float g_H[BATCH * DIM];     // gathered h_e rows (fp32, coefs)
__device__ __align__(16) __nv_bfloat16 g_Ah[BATCH * DIM];   // A hi
__device__ __align__(16) __nv_bfloat16 g_Al[BATCH * DIM];   // A lo
__device__ __align__(16) __nv_bfloat16 g_Bth[NMAXPAD * DIM]; // B^T hi  [n][k]
__device__ __align__(16) __nv_bfloat16 g_Btl[NMAXPAD * DIM]; // B^T lo  [n][k]
__device__ float        g_r0[BATCH];               // rel[r[i]][0]
__device__ unsigned int g_xmax_bits;               // max |h_e| over gathered rows
__device__ int          g_class[CH];               // 0=zero 1=linear 2=uncertain
__device__ int          g_unc[CH];                 // compact list of uncertain channels
__device__ int          g_uidx[CH];                // channel -> index in g_unc
__device__ int          g_N;                       // runtime #columns = 545 + 511*U

#define MMA_BF16(C, A, B0, B1) \
    asm volatile("mma.sync.aligned.m16n8k16.row.col.f32.bf16.bf16.f32 " \
        "{%0,%1,%2,%3},{%4,%5,%6,%7},{%8,%9},{%0,%1,%2,%3};" \
        : "+f"(C[0]), "+f"(C[1]), "+f"(C[2]), "+f"(C[3]) \
        : "r"(A[0]), "r"(A[1]), "r"(A[2]), "r"(A[3]), "r"(B0), "r"(B1))

#define LDSM_X4(d0, d1, d2, d3, addr) \
    asm volatile("ldmatrix.sync.aligned.m8n8.x4.shared.b16 {%0,%1,%2,%3}, [%4];" \
        : "=r"(d0), "=r"(d1), "=r"(d2), "=r"(d3) : "r"(addr))

#define CP_ASYNC_16(dst, src) \
    asm volatile("cp.async.cg.shared.global [%0], [%1], 16;" :: "r"(dst), "l"(src))
#define CP_COMMIT() asm volatile("cp.async.commit_group;")
#define CP_WAIT1()  asm volatile("cp.async.wait_group 1;")
#define CP_WAIT0()  asm volatile("cp.async.wait_group 0;")

// -------------------- K0: init (zero scores + B's atomic-merge region) ------
__global__ __launch_bounds__(256) void k0_init(float* __restrict__ out) {
    int id = blockIdx.x * blockDim.x + threadIdx.x;
    if (id < BATCH) out[id] = 0.0f;
    if (id == 0) g_xmax_bits = 0u;
    const int total = 512 * 513;
    if (id < total) {
        int d = id / 513;
        int n = id - d * 513;
        g_B[(size_t)d * LDB + n] = 0.0f;
    }
}

// ------------------- K1: gather rows + max|h_e| + A hi/lo split -------------
__global__ __launch_bounds__(128) void k1_gather(
    const int* __restrict__ h, const int* __restrict__ r, const int* __restrict__ t,
    const float* __restrict__ ent, const float* __restrict__ rel)
{
    int i = blockIdx.x;
    int tid = threadIdx.x;               // 128 threads, one float4 each
    const float4* hs = (const float4*)(ent + (size_t)h[i] * DIM);
    const float4* ts = (const float4*)(ent + (size_t)t[i] * DIM);
    float4 hv = hs[tid];
    float4 tv = ts[tid];
    ((float4*)g_H)[i * 128 + tid] = hv;
    {
        float v[4] = {tv.x, tv.y, tv.z, tv.w};
        size_t base = (size_t)i * DIM + tid * 4;
        #pragma unroll
        for (int j = 0; j < 4; j++) {
            __nv_bfloat16 hi = __float2bfloat16(v[j]);
            __nv_bfloat16 lo = __float2bfloat16(v[j] - __bfloat162float(hi));
            g_Ah[base + j] = hi;
            g_Al[base + j] = lo;
        }
    }
    float m = fmaxf(fmaxf(fabsf(hv.x), fabsf(hv.y)), fmaxf(fabsf(hv.z), fabsf(hv.w)));
    #pragma unroll
    for (int off = 16; off > 0; off >>= 1)
        m = fmaxf(m, __shfl_xor_sync(0xffffffffu, m, off));
    __shared__ float wm[4];
    if ((tid & 31) == 0) wm[tid >> 5] = m;
    __syncthreads();
    if (tid == 0) {
        float mm = fmaxf(fmaxf(wm[0], wm[1]), fmaxf(wm[2], wm[3]));
        atomicMax(&g_xmax_bits, __float_as_uint(mm));
        g_r0[i] = rel[(size_t)r[i] * DIM];
    }
}

// ------------------------------------------- K2: per-channel classification
__global__ void k2_classify(const float* __restrict__ cw, const float* __restrict__ cb) {
    int c = threadIdx.x;                 // 32 threads (one full warp)
    float xmax = __uint_as_float(g_xmax_bits);
    float bound = (fabsf(cw[c * 3 + 0]) + fabsf(cw[c * 3 + 1]) + fabsf(cw[c * 3 + 2])) * xmax;
    float b = cb[c];
    int cls = (b >= bound) ? 1 : ((b <= -bound) ? 0 : 2);
    g_class[c] = cls;
    unsigned m = __ballot_sync(0xffffffffu, cls == 2);
    if (cls == 2) {
        int idx = __popc(m & ((1u << c) - 1u));
        g_unc[idx] = c;
        g_uidx[c] = idx;
    }
    if (c == 0) g_N = 545 + 511 * __popc(m);
}

// ------------------------------------------- K3: fold conv+proj_w into B
__global__ __launch_bounds__(256) void k3_build(
    const float* __restrict__ pw, const float* __restrict__ pb,
    const float* __restrict__ cw, const float* __restrict__ cb)
{
    int bx = blockIdx.x;                 // 1024 blocks
    int d = bx >> 1;
    int half = bx & 1;
    int t = threadIdx.x;                 // 256 threads
    __shared__ __align__(16) float seg[16 * 512];   // 32KB: 16 channels
    __shared__ float red[256];
    float acc0 = 0.0f, acc1 = 0.0f;
    float cpart = 0.0f;
    const float* prow = pw + (size_t)d * (CH * DIM) + half * 16 * 512;
    size_t brow = (size_t)d * LDB;
    const int n1 = t + 256;

    const float4* src = (const float4*)prow;
    #pragma unroll
    for (int j = 0; j < 8; j++)
        ((float4*)seg)[t + j * 256] = src[t + j * 256];
    __syncthreads();

    #pragma unroll 1
    for (int cc = 0; cc < 16; cc++) {
        int c = half * 16 + cc;
        const float* s = seg + cc * 512;
        int cls = g_class[c];
        if (t == 0) g_B[brow + 513 + c] = s[511];        // edge column (p==511)
        if (cls == 1) {
            float w0 = cw[c * 3 + 0], w1 = cw[c * 3 + 1], w2 = cw[c * 3 + 2];
            float bc = cb[c];
            {
                float s0  = s[t];
                float sp1 = s[t + 1];
                float v = fmaf(w0, sp1, w1 * s0);
                if (t >= 1) v = fmaf(w2, s[t - 1], v);
                acc0 += v;
                cpart = fmaf(bc, s0, cpart);
            }
            {
                float v = w2 * s[n1 - 1];
                if (n1 <= 510) v = fmaf(w1, s[n1], v);
                if (n1 <= 509) v = fmaf(w0, s[n1 + 1], v);
                acc1 += v;
                if (n1 <= 510) cpart = fmaf(bc, s[n1], cpart);
            }
        } else if (cls == 2) {
            size_t base = brow + 545 + (size_t)g_uidx[c] * 511;
            g_B[base + t] = s[t];
            if (n1 < 511) g_B[base + n1] = s[n1];
        }
    }
    atomicAdd(&g_B[brow + t],  acc0);
    atomicAdd(&g_B[brow + n1], acc1);
    red[t] = cpart;
    __syncthreads();
    #pragma unroll
    for (int sfd = 128; sfd > 0; sfd >>= 1) {
        if (t < sfd) red[t] += red[t + sfd];
        __syncthreads();
    }
    if (t == 0) {
        float v = red[0] + (half == 0 ? pb[d] : 0.0f);
        atomicAdd(&g_B[brow + 512], v);                  // const column
    }
}

// -------------------- K3.5: transpose + hi/lo split B -> Bt[n][k] -----------
__global__ __launch_bounds__(256) void k35_convertB() {
    const int Ncols = g_N;
    int n0 = blockIdx.y * 32;
    if (n0 >= ((Ncols + 63) & ~63)) return;   // cover full 64-wide k4 tiles
    int k0 = blockIdx.x * 32;
    __shared__ float tile[32][33];
    int tx = threadIdx.x & 31, ty = threadIdx.x >> 5;   // ty 0..7
    #pragma unroll
    for (int rr = 0; rr < 4; rr++) {
        int kk = ty + rr * 8;
        tile[kk][tx] = g_B[(size_t)(k0 + kk) * LDB + n0 + tx];
    }
    __syncthreads();
    #pragma unroll
    for (int rr = 0; rr < 4; rr++) {
        int nn = ty + rr * 8;
        float v = tile[tx][nn];
        __nv_bfloat16 hv = __float2bfloat16(v);
        float lv = v - __bfloat162float(hv);
        g_Bth[(size_t)(n0 + nn) * DIM + k0 + tx] = hv;
        g_Btl[(size_t)(n0 + nn) * DIM + k0 + tx] = __float2bfloat16(lv);
    }
}

// -------------------- coef(row, col) for the scoring epilogue ---------------
__device__ __forceinline__ float coef_fn(int row, int n, int Ncols,
                                         const float* __restrict__ cw,
                                         const float* __restrict__ cb)
{
    if (n >= Ncols) return 0.0f;
    if (n < 512)  return g_H[(size_t)row * DIM + n];
    if (n == 512) return 1.0f;
    const float* Hr = &g_H[(size_t)row * DIM];
    if (n < 545) {
        int c = n - 513;
        float v = fmaf(cw[c * 3], Hr[510],
                  fmaf(cw[c * 3 + 1], Hr[511],
                  fmaf(cw[c * 3 + 2], g_r0[row], cb[c])));
        return fmaxf(v, 0.0f);
    }
    int q = n - 545;
    int ui = q / 511;
    int p = q - ui * 511;                // p in [0, 510]
    int c = g_unc[ui];
    float xm1 = (p == 0) ? 0.0f : Hr[p - 1];
    float v = fmaf(cw[c * 3], xm1,
              fmaf(cw[c * 3 + 1], Hr[p],
              fmaf(cw[c * 3 + 2], Hr[p + 1], cb[c])));
    return fmaxf(v, 0.0f);
}

// -------------------- K4: tensor-core GEMM + fused scoring ------------------
// 128(m) x 64(n) tile, k-tile 16, 2-stage cp.async pipeline, ldmatrix frags.
// STATIC smem, rows padded to 24 bf16 (48B stride -> ldmatrix conflict-free,
// 16B chunks stay 16B-aligned). Stage layout (bf16-element offsets):
//   AH +0 (128x24), AL +3072, BH +6144 (64x24), BL +7680; stage stride 9216.
#define K4_STRIDE 24
#define K4_STAGE  9216

__global__ __launch_bounds__(256) void k4_gemm(
    const float* __restrict__ cw, const float* __restrict__ cb,
    float* __restrict__ out)
{
    const int Ncols = g_N;
    const int n0 = blockIdx.x * 64;
    if (n0 >= Ncols) return;
    const int m0 = blockIdx.y * 128;

    __shared__ __align__(16) __nv_bfloat16 smem[2 * K4_STAGE];   // 36,864 B
    const unsigned sbase = (unsigned)__cvta_generic_to_shared(smem);

    const int tid  = threadIdx.x;
    const int lane = tid & 31;
    const int warp = tid >> 5;
    const int g = lane >> 2;             // 0..7
    const int q = lane & 3;              // 0..3
    const int wm = warp >> 2;            // 0..1
    const int wn = warp & 3;             // 0..3

    float c_[4][2][4];
    #pragma unroll
    for (int s = 0; s < 4; s++)
        #pragma unroll
        for (int u = 0; u < 2; u++)
            #pragma unroll
            for (int e = 0; e < 4; e++) c_[s][u][e] = 0.0f;

    // per-thread cp.async mapping
    const int a_row  = tid >> 1;         // 0..127
    const int a_half = (tid & 1) * 8;    // 0 or 8
    const int b_row  = (tid & 127) >> 1; // 0..63
    const int b_half = (tid & 1) * 8;

    auto load_stage = [&](int st, int k0) {
        unsigned stb = sbase + (unsigned)(st * K4_STAGE) * 2;
        const __nv_bfloat16* sAh = g_Ah + (size_t)(m0 + a_row) * DIM + k0 + a_half;
        const __nv_bfloat16* sAl = g_Al + (size_t)(m0 + a_row) * DIM + k0 + a_half;
        unsigned dA = stb + (unsigned)(a_row * K4_STRIDE + a_half) * 2;
        CP_ASYNC_16(dA, sAh);
        CP_ASYNC_16(dA + 3072 * 2, sAl);
        if (tid < 128) {
            const __nv_bfloat16* sBh = g_Bth + (size_t)(n0 + b_row) * DIM + k0 + b_half;
            const __nv_bfloat16* sBl = g_Btl + (size_t)(n0 + b_row) * DIM + k0 + b_half;
            unsigned dB = stb + (unsigned)(6144 + b_row * K4_STRIDE + b_half) * 2;
            CP_ASYNC_16(dB, sBh);
            CP_ASYNC_16(dB + 1536 * 2, sBl);
        }
    };

    load_stage(0, 0);
    CP_COMMIT();

    // ldmatrix lane addressing (element offsets within a stage)
    const int a_r = lane & 15;                        // row within 16-row subtile
    const int a_c = (lane >> 4) << 3;                 // 0 or 8 (k-half)
    const int b_r = ((lane >> 4) << 3) + (lane & 7);  // row within 16-n slice
    const int b_c = ((lane >> 3) & 1) << 3;           // 0 or 8 (k-half)

    #pragma unroll 1
    for (int it = 0; it < 32; it++) {
        const int cur = it & 1;
        if (it < 31) {
            load_stage(cur ^ 1, (it + 1) * 16);
            CP_COMMIT();
            CP_WAIT1();
        } else {
            CP_WAIT0();
        }
        __syncthreads();

        unsigned stb = sbase + (unsigned)(cur * K4_STAGE) * 2;
        unsigned afh[4][4], afl[4][4], bh[4], bl[4];
        #pragma unroll
        for (int s = 0; s < 4; s++) {
            int r = wm * 64 + s * 16 + a_r;
            unsigned aH = stb + (unsigned)(r * K4_STRIDE + a_c) * 2;
            LDSM_X4(afh[s][0], afh[s][1], afh[s][2], afh[s][3], aH);
            LDSM_X4(afl[s][0], afl[s][1], afl[s][2], afl[s][3], aH + 3072 * 2);
        }
        {
            int r = wn * 16 + b_r;
            unsigned aB = stb + (unsigned)(6144 + r * K4_STRIDE + b_c) * 2;
            LDSM_X4(bh[0], bh[1], bh[2], bh[3], aB);
            LDSM_X4(bl[0], bl[1], bl[2], bl[3], aB + 1536 * 2);
        }
        #pragma unroll
        for (int s = 0; s < 4; s++)
            #pragma unroll
            for (int u = 0; u < 2; u++) {
                MMA_BF16(c_[s][u], afh[s], bh[2 * u], bh[2 * u + 1]);
                MMA_BF16(c_[s][u], afh[s], bl[2 * u], bl[2 * u + 1]);
                MMA_BF16(c_[s][u], afl[s], bh[2 * u], bh[2 * u + 1]);
            }
        __syncthreads();
    }

    // epilogue: coef-weighted reduction, then width-4 shfl + atomicAdd
    #pragma unroll
    for (int s = 0; s < 4; s++) {
        int row0 = m0 + wm * 64 + s * 16 + g;
        int row1 = row0 + 8;
        float rs0 = 0.0f, rs1 = 0.0f;
        #pragma unroll
        for (int u = 0; u < 2; u++) {
            int n = n0 + wn * 16 + u * 8 + 2 * q;
            float cf00 = coef_fn(row0, n,     Ncols, cw, cb);
            float cf01 = coef_fn(row0, n + 1, Ncols, cw, cb);
            float cf10 = coef_fn(row1, n,     Ncols, cw, cb);
            float cf11 = coef_fn(row1, n + 1, Ncols, cw, cb);
            rs0 = fmaf(c_[s][u][0], cf00, fmaf(c_[s][u][1], cf01, rs0));
            rs1 = fmaf(c_[s][u][2], cf10, fmaf(c_[s][u][3], cf11, rs1));
        }
        rs0 += __shfl_down_sync(0xffffffffu, rs0, 2, 4);
        rs0 += __shfl_down_sync(0xffffffffu, rs0, 1, 4);
        rs1 += __shfl_down_sync(0xffffffffu, rs1, 2, 4);
        rs1 += __shfl_down_sync(0xffffffffu, rs1, 1, 4);
        if (q == 0) {
            atomicAdd(&out[row0], rs0);
            atomicAdd(&out[row1], rs1);
        }
    }
}

// ---------------------------------------------------------------------------
extern "C" void kernel_launch(void* const* d_in, const int* in_sizes, int n_in,
                              void* d_out, int out_size)
{
    const int*   h      = (const int*)  d_in[0];
    const int*   r      = (const int*)  d_in[1];
    const int*   t      = (const int*)  d_in[2];
    const float* ent    = (const float*)d_in[3];
    const float* rel    = (const float*)d_in[4];
    const float* conv_w = (const float*)d_in[5];
    const float* conv_b = (const float*)d_in[6];
    const float* proj_w = (const float*)d_in[7];
    const float* proj_b = (const float*)d_in[8];
    float* out = (float*)d_out;

    k0_init<<<1032, 256>>>(out);
    k1_gather<<<BATCH, 128>>>(h, r, t, ent, rel);
    k2_classify<<<1, 32>>>(conv_w, conv_b);
    k3_build<<<1024, 256>>>(proj_w, proj_b, conv_w, conv_b);
    k35_convertB<<<dim3(16, 530), 256>>>();
    // worst-case grid over columns (N known only on device); blocks past N exit
    k4_gemm<<<dim3(265, 16), 256>>>(conv_w, conv_b, out);
}

// round 9
// speedup vs baseline: 1.8848x; 1.0910x over previous
#include <cuda_runtime.h>
#include <cuda_bf16.h>

// ---------------------------------------------------------------------------
// ConvTransE scoring, algebraically reduced:
//   score[i] = e_t[i]^T (proj_w @ relu(conv(x_i)+b) + proj_b),  x_i = [h_e ; r_e]
// Linear/zero channels folded into an effective 512x512 matrix; the few
// "uncertain" channels + the p==511 edge go through exact-ReLU correction
// columns of one fused GEMM. Tensor cores via hi/lo bf16 split (3x mma.sync
// m16n8k16), ldmatrix fragments, 4-stage cp.async pipeline in STATIC smem.
// ---------------------------------------------------------------------------

#define BATCH    2048
#define DIM      512
#define CH       32
#define LDB      16960          // >= 265*64, float4-aligned row stride of B
#define NMAXPAD  16960

__device__ __align__(16) float g_B[512 * LDB];       // built GEMM B matrix (fp32)
__device__ __align__(16) float g_H[BATCH * DIM];     // gathered h_e rows (fp32, coefs)
__device__ __align__(16) __nv_bfloat16 g_Ah[BATCH * DIM];   // A hi
__device__ __align__(16) __nv_bfloat16 g_Al[BATCH * DIM];   // A lo
__device__ __align__(16) __nv_bfloat16 g_Bth[NMAXPAD * DIM]; // B^T hi  [n][k]
__device__ __align__(16) __nv_bfloat16 g_Btl[NMAXPAD * DIM]; // B^T lo  [n][k]
__device__ float        g_r0[BATCH];               // rel[r[i]][0]
__device__ unsigned int g_xmax_bits;               // max |h_e| over gathered rows
__device__ int          g_class[CH];               // 0=zero 1=linear 2=uncertain
__device__ int          g_unc[CH];                 // compact list of uncertain channels
__device__ int          g_uidx[CH];                // channel -> index in g_unc
__device__ int          g_N;                       // runtime #columns = 545 + 511*U

#define MMA_BF16(C, A, B0, B1) \
    asm volatile("mma.sync.aligned.m16n8k16.row.col.f32.bf16.bf16.f32 " \
        "{%0,%1,%2,%3},{%4,%5,%6,%7},{%8,%9},{%0,%1,%2,%3};" \
        : "+f"(C[0]), "+f"(C[1]), "+f"(C[2]), "+f"(C[3]) \
        : "r"(A[0]), "r"(A[1]), "r"(A[2]), "r"(A[3]), "r"(B0), "r"(B1))

#define LDSM_X4(d0, d1, d2, d3, addr) \
    asm volatile("ldmatrix.sync.aligned.m8n8.x4.shared.b16 {%0,%1,%2,%3}, [%4];" \
        : "=r"(d0), "=r"(d1), "=r"(d2), "=r"(d3) : "r"(addr))

#define CP_ASYNC_16(dst, src) \
    asm volatile("cp.async.cg.shared.global [%0], [%1], 16;" :: "r"(dst), "l"(src))
#define CP_COMMIT() asm volatile("cp.async.commit_group;")
#define CP_WAIT2()  asm volatile("cp.async.wait_group 2;")
#define CP_WAIT1()  asm volatile("cp.async.wait_group 1;")
#define CP_WAIT0()  asm volatile("cp.async.wait_group 0;")

// -------------------- K0: init (zero scores only; B fully overwritten) ------
__global__ __launch_bounds__(256) void k0_init(float* __restrict__ out) {
    int id = blockIdx.x * blockDim.x + threadIdx.x;
    if (id < BATCH) out[id] = 0.0f;
    if (id == 0) g_xmax_bits = 0u;
}

// ------------------- K1: gather rows + max|h_e| + A hi/lo split -------------
__global__ __launch_bounds__(128) void k1_gather(
    const int* __restrict__ h, const int* __restrict__ r, const int* __restrict__ t,
    const float* __restrict__ ent, const float* __restrict__ rel)
{
    int i = blockIdx.x;
    int tid = threadIdx.x;               // 128 threads, one float4 each
    const float4* hs = (const float4*)(ent + (size_t)h[i] * DIM);
    const float4* ts = (const float4*)(ent + (size_t)t[i] * DIM);
    float4 hv = hs[tid];
    float4 tv = ts[tid];
    ((float4*)g_H)[i * 128 + tid] = hv;
    {
        float v[4] = {tv.x, tv.y, tv.z, tv.w};
        size_t base = (size_t)i * DIM + tid * 4;
        #pragma unroll
        for (int j = 0; j < 4; j++) {
            __nv_bfloat16 hi = __float2bfloat16(v[j]);
            __nv_bfloat16 lo = __float2bfloat16(v[j] - __bfloat162float(hi));
            g_Ah[base + j] = hi;
            g_Al[base + j] = lo;
        }
    }
    float m = fmaxf(fmaxf(fabsf(hv.x), fabsf(hv.y)), fmaxf(fabsf(hv.z), fabsf(hv.w)));
    #pragma unroll
    for (int off = 16; off > 0; off >>= 1)
        m = fmaxf(m, __shfl_xor_sync(0xffffffffu, m, off));
    __shared__ float wm[4];
    if ((tid & 31) == 0) wm[tid >> 5] = m;
    __syncthreads();
    if (tid == 0) {
        float mm = fmaxf(fmaxf(wm[0], wm[1]), fmaxf(wm[2], wm[3]));
        atomicMax(&g_xmax_bits, __float_as_uint(mm));
        g_r0[i] = rel[(size_t)r[i] * DIM];
    }
}

// ------------------------------------------- K2: per-channel classification
__global__ void k2_classify(const float* __restrict__ cw, const float* __restrict__ cb) {
    int c = threadIdx.x;                 // 32 threads (one full warp)
    float xmax = __uint_as_float(g_xmax_bits);
    float bound = (fabsf(cw[c * 3 + 0]) + fabsf(cw[c * 3 + 1]) + fabsf(cw[c * 3 + 2])) * xmax;
    float b = cb[c];
    int cls = (b >= bound) ? 1 : ((b <= -bound) ? 0 : 2);
    g_class[c] = cls;
    unsigned m = __ballot_sync(0xffffffffu, cls == 2);
    if (cls == 2) {
        int idx = __popc(m & ((1u << c) - 1u));
        g_unc[idx] = c;
        g_uidx[c] = idx;
    }
    if (c == 0) g_N = 545 + 511 * __popc(m);
}

// ------------------------------------------- K3: fold conv+proj_w into B
// Streaming register fold: acc[n] = T0[n+1] + T1[n] + T2[n-1] with
// Tj[n] = sum_c wj_c * s_c[n] (linear channels only). Two warps per d-row
// (16 channels each), merged through one smem exchange; boundaries via shfl.
// No atomics, no per-channel sync.
__global__ __launch_bounds__(256) void k3_build(
    const float* __restrict__ pw, const float* __restrict__ pb,
    const float* __restrict__ cw, const float* __restrict__ cb)
{
    __shared__ float sT[4][4][512];      // 32KB partials from half-1 warps
    const int warp = threadIdx.x >> 5;
    const int lane = threadIdx.x & 31;
    const int rl = warp >> 1;            // row-local 0..3
    const int hc = warp & 1;             // channel half
    const int d  = blockIdx.x * 4 + rl;
    const float* prow = pw + (size_t)d * (CH * DIM);
    const size_t brow = (size_t)d * LDB;
    const int n0 = lane * 16;

    float T0[16], T1[16], T2[16], T3[16];
    #pragma unroll
    for (int j = 0; j < 16; j++) { T0[j] = 0.f; T1[j] = 0.f; T2[j] = 0.f; T3[j] = 0.f; }

    #pragma unroll 2
    for (int cc = 0; cc < 16; cc++) {
        const int c = hc * 16 + cc;
        const float4* sp = (const float4*)(prow + c * DIM + n0);
        float4 a0 = sp[0], a1 = sp[1], a2 = sp[2], a3 = sp[3];
        float s[16] = {a0.x,a0.y,a0.z,a0.w, a1.x,a1.y,a1.z,a1.w,
                       a2.x,a2.y,a2.z,a2.w, a3.x,a3.y,a3.z,a3.w};
        int cls = g_class[c];
        if (lane == 31) g_B[brow + 513 + c] = s[15];     // edge col (p==511)
        if (cls == 1) {
            float w0 = cw[c*3], w1 = cw[c*3+1], w2 = cw[c*3+2], bc = cb[c];
            #pragma unroll
            for (int j = 0; j < 16; j++) {
                T0[j] = fmaf(w0, s[j], T0[j]);
                T1[j] = fmaf(w1, s[j], T1[j]);
                T2[j] = fmaf(w2, s[j], T2[j]);
                T3[j] = fmaf(bc, s[j], T3[j]);
            }
        } else if (cls == 2) {
            size_t base = brow + 545 + (size_t)g_uidx[c] * 511 + n0;
            #pragma unroll
            for (int j = 0; j < 16; j++)
                if (n0 + j < 511) g_B[base + j] = s[j];  // scalar (base not 16B-aligned)
        }
    }

    if (hc == 1) {
        #pragma unroll
        for (int j = 0; j < 16; j++) {
            sT[rl][0][n0 + j] = T0[j];
            sT[rl][1][n0 + j] = T1[j];
            sT[rl][2][n0 + j] = T2[j];
            sT[rl][3][n0 + j] = T3[j];
        }
    }
    __syncthreads();
    if (hc == 0) {
        #pragma unroll
        for (int j = 0; j < 16; j++) {
            T0[j] += sT[rl][0][n0 + j];
            T1[j] += sT[rl][1][n0 + j];
            T2[j] += sT[rl][2][n0 + j];
            T3[j] += sT[rl][3][n0 + j];
        }
        float t0n = __shfl_down_sync(0xffffffffu, T0[0], 1);   // T0[n0+16]
        float t2p = __shfl_up_sync(0xffffffffu, T2[15], 1);    // T2[n0-1]
        float acc[16];
        #pragma unroll
        for (int j = 0; j < 16; j++) {
            int n = n0 + j;
            float t0 = (j < 15) ? T0[j + 1] : t0n;
            float t2 = (j > 0) ? T2[j - 1] : t2p;
            float v = 0.0f;
            if (n <= 509) v += t0;
            if (n <= 510) v += T1[j];
            if (n >= 1)   v += t2;
            acc[j] = v;
        }
        float4* dst = (float4*)&g_B[brow + n0];
        dst[0] = make_float4(acc[0],  acc[1],  acc[2],  acc[3]);
        dst[1] = make_float4(acc[4],  acc[5],  acc[6],  acc[7]);
        dst[2] = make_float4(acc[8],  acc[9],  acc[10], acc[11]);
        dst[3] = make_float4(acc[12], acc[13], acc[14], acc[15]);
        float tsum = 0.0f;
        #pragma unroll
        for (int j = 0; j < 16; j++)
            if (n0 + j <= 510) tsum += T3[j];
        #pragma unroll
        for (int off = 16; off > 0; off >>= 1)
            tsum += __shfl_xor_sync(0xffffffffu, tsum, off);
        if (lane == 0) g_B[brow + 512] = tsum + pb[d];   // const column
    }
}

// -------------------- K3.5: transpose + hi/lo split B -> Bt[n][k] -----------
__global__ __launch_bounds__(256) void k35_convertB() {
    const int Ncols = g_N;
    int n0 = blockIdx.y * 32;
    if (n0 >= ((Ncols + 63) & ~63)) return;   // cover full 64-wide k4 tiles
    int k0 = blockIdx.x * 32;
    __shared__ float tile[32][33];
    int tx = threadIdx.x & 31, ty = threadIdx.x >> 5;   // ty 0..7
    #pragma unroll
    for (int rr = 0; rr < 4; rr++) {
        int kk = ty + rr * 8;
        tile[kk][tx] = g_B[(size_t)(k0 + kk) * LDB + n0 + tx];
    }
    __syncthreads();
    #pragma unroll
    for (int rr = 0; rr < 4; rr++) {
        int nn = ty + rr * 8;
        float v = tile[tx][nn];
        __nv_bfloat16 hv = __float2bfloat16(v);
        float lv = v - __bfloat162float(hv);
        g_Bth[(size_t)(n0 + nn) * DIM + k0 + tx] = hv;
        g_Btl[(size_t)(n0 + nn) * DIM + k0 + tx] = __float2bfloat16(lv);
    }
}

// -------------------- coef(row, col) for the scoring epilogue ---------------
__device__ __forceinline__ float coef_fn(int row, int n, int Ncols,
                                         const float* __restrict__ cw,
                                         const float* __restrict__ cb)
{
    if (n >= Ncols) return 0.0f;
    if (n < 512)  return g_H[(size_t)row * DIM + n];
    if (n == 512) return 1.0f;
    const float* Hr = &g_H[(size_t)row * DIM];
    if (n < 545) {
        int c = n - 513;
        float v = fmaf(cw[c * 3], Hr[510],
                  fmaf(cw[c * 3 + 1], Hr[511],
                  fmaf(cw[c * 3 + 2], g_r0[row], cb[c])));
        return fmaxf(v, 0.0f);
    }
    int q = n - 545;
    int ui = q / 511;
    int p = q - ui * 511;                // p in [0, 510]
    int c = g_unc[ui];
    float xm1 = (p == 0) ? 0.0f : Hr[p - 1];
    float v = fmaf(cw[c * 3], xm1,
              fmaf(cw[c * 3 + 1], Hr[p],
              fmaf(cw[c * 3 + 2], Hr[p + 1], cb[c])));
    return fmaxf(v, 0.0f);
}

// -------------------- K4: tensor-core GEMM + fused scoring ------------------
// 64(m) x 64(n) tile, k-tile 16, 4-stage cp.async ring (48KB static smem,
// one __syncthreads per iteration), ldmatrix fragments, rows padded to
// 24 bf16 (48B stride -> conflict-free, 16B-aligned chunks).
// Stage layout (bf16 elements): AH 0 (64x24), AL 1536, BH 3072, BL 4608.
#define K4_STRIDE 24
#define K4_STAGE  6144

__global__ __launch_bounds__(128) void k4_gemm(
    const float* __restrict__ cw, const float* __restrict__ cb,
    float* __restrict__ out)
{
    const int Ncols = g_N;
    const int n0 = blockIdx.x * 64;
    if (n0 >= Ncols) return;
    const int m0 = blockIdx.y * 64;

    __shared__ __align__(16) __nv_bfloat16 smem[4 * K4_STAGE];   // 49,152 B
    const unsigned sbase = (unsigned)__cvta_generic_to_shared(smem);

    const int tid  = threadIdx.x;
    const int lane = tid & 31;
    const int wn   = tid >> 5;           // 0..3 (n 16-offset)
    const int g = lane >> 2;             // 0..7
    const int q = lane & 3;              // 0..3

    float c_[4][2][4];
    #pragma unroll
    for (int s = 0; s < 4; s++)
        #pragma unroll
        for (int u = 0; u < 2; u++)
            #pragma unroll
            for (int e = 0; e < 4; e++) c_[s][u][e] = 0.0f;

    // per-thread cp.async mapping (128 threads, 4 x 16B each)
    const int l_row  = tid >> 1;         // 0..63
    const int l_half = (tid & 1) * 8;    // 0 or 8

    auto load_stage = [&](int st, int kc) {
        unsigned stb = sbase + (unsigned)(st * K4_STAGE) * 2;
        unsigned dA = stb + (unsigned)(l_row * K4_STRIDE + l_half) * 2;
        CP_ASYNC_16(dA,            g_Ah + (size_t)(m0 + l_row) * DIM + kc + l_half);
        CP_ASYNC_16(dA + 1536 * 2, g_Al + (size_t)(m0 + l_row) * DIM + kc + l_half);
        unsigned dB = stb + (unsigned)(3072 + l_row * K4_STRIDE + l_half) * 2;
        CP_ASYNC_16(dB,            g_Bth + (size_t)(n0 + l_row) * DIM + kc + l_half);
        CP_ASYNC_16(dB + 1536 * 2, g_Btl + (size_t)(n0 + l_row) * DIM + kc + l_half);
    };

    load_stage(0, 0);  CP_COMMIT();
    load_stage(1, 16); CP_COMMIT();
    load_stage(2, 32); CP_COMMIT();

    // ldmatrix lane addressing (element offsets within a stage)
    const int a_r = lane & 15;                        // row within 16-row subtile
    const int a_c = (lane >> 4) << 3;                 // 0 or 8 (k-half)
    const int b_r = ((lane >> 4) << 3) + (lane & 7);  // row within 16-n slice
    const int b_c = ((lane >> 3) & 1) << 3;           // 0 or 8 (k-half)

    #pragma unroll 1
    for (int it = 0; it < 32; it++) {
        if (it < 30) { CP_WAIT2(); }
        else if (it == 30) { CP_WAIT1(); }
        else { CP_WAIT0(); }
        __syncthreads();
        if (it < 29) { load_stage((it + 3) & 3, (it + 3) * 16); CP_COMMIT(); }

        unsigned stb = sbase + (unsigned)((it & 3) * K4_STAGE) * 2;
        unsigned afh[4][4], afl[4][4], bh[4], bl[4];
        #pragma unroll
        for (int s = 0; s < 4; s++) {
            int r = s * 16 + a_r;
            unsigned aH = stb + (unsigned)(r * K4_STRIDE + a_c) * 2;
            LDSM_X4(afh[s][0], afh[s][1], afh[s][2], afh[s][3], aH);
            LDSM_X4(afl[s][0], afl[s][1], afl[s][2], afl[s][3], aH + 1536 * 2);
        }
        {
            int r = wn * 16 + b_r;
            unsigned aB = stb + (unsigned)(3072 + r * K4_STRIDE + b_c) * 2;
            LDSM_X4(bh[0], bh[1], bh[2], bh[3], aB);
            LDSM_X4(bl[0], bl[1], bl[2], bl[3], aB + 1536 * 2);
        }
        #pragma unroll
        for (int s = 0; s < 4; s++)
            #pragma unroll
            for (int u = 0; u < 2; u++) {
                MMA_BF16(c_[s][u], afh[s], bh[2 * u], bh[2 * u + 1]);
                MMA_BF16(c_[s][u], afh[s], bl[2 * u], bl[2 * u + 1]);
                MMA_BF16(c_[s][u], afl[s], bh[2 * u], bh[2 * u + 1]);
            }
    }

    // epilogue: coef-weighted reduction, then width-4 shfl + atomicAdd
    #pragma unroll
    for (int s = 0; s < 4; s++) {
        int row0 = m0 + s * 16 + g;
        int row1 = row0 + 8;
        float rs0 = 0.0f, rs1 = 0.0f;
        #pragma unroll
        for (int u = 0; u < 2; u++) {
            int n = n0 + wn * 16 + u * 8 + 2 * q;
            float cf00 = coef_fn(row0, n,     Ncols, cw, cb);
            float cf01 = coef_fn(row0, n + 1, Ncols, cw, cb);
            float cf10 = coef_fn(row1, n,     Ncols, cw, cb);
            float cf11 = coef_fn(row1, n + 1, Ncols, cw, cb);
            rs0 = fmaf(c_[s][u][0], cf00, fmaf(c_[s][u][1], cf01, rs0));
            rs1 = fmaf(c_[s][u][2], cf10, fmaf(c_[s][u][3], cf11, rs1));
        }
        rs0 += __shfl_down_sync(0xffffffffu, rs0, 2, 4);
        rs0 += __shfl_down_sync(0xffffffffu, rs0, 1, 4);
        rs1 += __shfl_down_sync(0xffffffffu, rs1, 2, 4);
        rs1 += __shfl_down_sync(0xffffffffu, rs1, 1, 4);
        if (q == 0) {
            atomicAdd(&out[row0], rs0);
            atomicAdd(&out[row1], rs1);
        }
    }
}

// ---------------------------------------------------------------------------
extern "C" void kernel_launch(void* const* d_in, const int* in_sizes, int n_in,
                              void* d_out, int out_size)
{
    const int*   h      = (const int*)  d_in[0];
    const int*   r      = (const int*)  d_in[1];
    const int*   t      = (const int*)  d_in[2];
    const float* ent    = (const float*)d_in[3];
    const float* rel    = (const float*)d_in[4];
    const float* conv_w = (const float*)d_in[5];
    const float* conv_b = (const float*)d_in[6];
    const float* proj_w = (const float*)d_in[7];
    const float* proj_b = (const float*)d_in[8];
    float* out = (float*)d_out;

    k0_init<<<8, 256>>>(out);
    k1_gather<<<BATCH, 128>>>(h, r, t, ent, rel);
    k2_classify<<<1, 32>>>(conv_w, conv_b);
    k3_build<<<128, 256>>>(proj_w, proj_b, conv_w, conv_b);
    k35_convertB<<<dim3(16, 530), 256>>>();
    // worst-case grid over columns (N known only on device); blocks past N exit
    k4_gemm<<<dim3(265, 32), 128>>>(conv_w, conv_b, out);
}

// round 10
// speedup vs baseline: 2.6921x; 1.4284x over previous
#include <cuda_runtime.h>
#include <cuda_bf16.h>

// ---------------------------------------------------------------------------
// ConvTransE scoring, algebraically reduced:
//   score[i] = e_t[i]^T (proj_w @ relu(conv(x_i)+b) + proj_b),  x_i = [h_e ; r_e]
// Linear/zero channels folded into an effective 512x512 matrix; the few
// "uncertain" channels + the p==511 edge go through exact-ReLU correction
// columns of one fused GEMM. Tensor cores via hi/lo bf16 split (3x mma.sync
// m16n8k16), ldmatrix fragments, 4-stage cp.async pipeline in STATIC smem.
// K4/K35 are persistent grid-stride kernels: no dead worst-case blocks.
// ---------------------------------------------------------------------------

#define BATCH    2048
#define DIM      512
#define CH       32
#define LDB      16960          // >= 265*64, float4-aligned row stride of B
#define NMAXPAD  16960

__device__ __align__(16) float g_B[512 * LDB];       // built GEMM B matrix (fp32)
__device__ __align__(16) float g_H[BATCH * DIM];     // gathered h_e rows (fp32, coefs)
__device__ __align__(16) __nv_bfloat16 g_Ah[BATCH * DIM];   // A hi
__device__ __align__(16) __nv_bfloat16 g_Al[BATCH * DIM];   // A lo
__device__ __align__(16) __nv_bfloat16 g_Bth[NMAXPAD * DIM]; // B^T hi  [n][k]
__device__ __align__(16) __nv_bfloat16 g_Btl[NMAXPAD * DIM]; // B^T lo  [n][k]
__device__ float        g_r0[BATCH];               // rel[r[i]][0]
__device__ unsigned int g_xmax_bits;               // max |h_e| over gathered rows
__device__ int          g_class[CH];               // 0=zero 1=linear 2=uncertain
__device__ int          g_unc[CH];                 // compact list of uncertain channels
__device__ int          g_uidx[CH];                // channel -> index in g_unc
__device__ int          g_N;                       // runtime #columns = 545 + 511*U

#define MMA_BF16(C, A, B0, B1) \
    asm volatile("mma.sync.aligned.m16n8k16.row.col.f32.bf16.bf16.f32 " \
        "{%0,%1,%2,%3},{%4,%5,%6,%7},{%8,%9},{%0,%1,%2,%3};" \
        : "+f"(C[0]), "+f"(C[1]), "+f"(C[2]), "+f"(C[3]) \
        : "r"(A[0]), "r"(A[1]), "r"(A[2]), "r"(A[3]), "r"(B0), "r"(B1))

#define LDSM_X4(d0, d1, d2, d3, addr) \
    asm volatile("ldmatrix.sync.aligned.m8n8.x4.shared.b16 {%0,%1,%2,%3}, [%4];" \
        : "=r"(d0), "=r"(d1), "=r"(d2), "=r"(d3) : "r"(addr))

#define CP_ASYNC_16(dst, src) \
    asm volatile("cp.async.cg.shared.global [%0], [%1], 16;" :: "r"(dst), "l"(src))
#define CP_COMMIT() asm volatile("cp.async.commit_group;")
#define CP_WAIT2()  asm volatile("cp.async.wait_group 2;")
#define CP_WAIT1()  asm volatile("cp.async.wait_group 1;")
#define CP_WAIT0()  asm volatile("cp.async.wait_group 0;")

// -------------------- K0: init (zero scores only; B regions static-zero) ----
__global__ __launch_bounds__(256) void k0_init(float* __restrict__ out) {
    int id = blockIdx.x * blockDim.x + threadIdx.x;
    if (id < BATCH) out[id] = 0.0f;
    if (id == 0) g_xmax_bits = 0u;
}

// ------------------- K1: gather rows + max|h_e| + A hi/lo split -------------
__global__ __launch_bounds__(128) void k1_gather(
    const int* __restrict__ h, const int* __restrict__ r, const int* __restrict__ t,
    const float* __restrict__ ent, const float* __restrict__ rel)
{
    int i = blockIdx.x;
    int tid = threadIdx.x;               // 128 threads, one float4 each
    const float4* hs = (const float4*)(ent + (size_t)h[i] * DIM);
    const float4* ts = (const float4*)(ent + (size_t)t[i] * DIM);
    float4 hv = hs[tid];
    float4 tv = ts[tid];
    ((float4*)g_H)[i * 128 + tid] = hv;
    {
        float v[4] = {tv.x, tv.y, tv.z, tv.w};
        size_t base = (size_t)i * DIM + tid * 4;
        #pragma unroll
        for (int j = 0; j < 4; j++) {
            __nv_bfloat16 hi = __float2bfloat16(v[j]);
            __nv_bfloat16 lo = __float2bfloat16(v[j] - __bfloat162float(hi));
            g_Ah[base + j] = hi;
            g_Al[base + j] = lo;
        }
    }
    float m = fmaxf(fmaxf(fabsf(hv.x), fabsf(hv.y)), fmaxf(fabsf(hv.z), fabsf(hv.w)));
    #pragma unroll
    for (int off = 16; off > 0; off >>= 1)
        m = fmaxf(m, __shfl_xor_sync(0xffffffffu, m, off));
    __shared__ float wm[4];
    if ((tid & 31) == 0) wm[tid >> 5] = m;
    __syncthreads();
    if (tid == 0) {
        float mm = fmaxf(fmaxf(wm[0], wm[1]), fmaxf(wm[2], wm[3]));
        atomicMax(&g_xmax_bits, __float_as_uint(mm));
        g_r0[i] = rel[(size_t)r[i] * DIM];
    }
}

// ------------------------------------------- K2: per-channel classification
__global__ void k2_classify(const float* __restrict__ cw, const float* __restrict__ cb) {
    int c = threadIdx.x;                 // 32 threads (one full warp)
    float xmax = __uint_as_float(g_xmax_bits);
    float bound = (fabsf(cw[c * 3 + 0]) + fabsf(cw[c * 3 + 1]) + fabsf(cw[c * 3 + 2])) * xmax;
    float b = cb[c];
    int cls = (b >= bound) ? 1 : ((b <= -bound) ? 0 : 2);
    g_class[c] = cls;
    unsigned m = __ballot_sync(0xffffffffu, cls == 2);
    if (cls == 2) {
        int idx = __popc(m & ((1u << c) - 1u));
        g_unc[idx] = c;
        g_uidx[c] = idx;
    }
    if (c == 0) g_N = 545 + 511 * __popc(m);
}

// ------------------------------------------- K3: fold conv+proj_w into B
// Streaming register fold: acc[n] = T0[n+1] + T1[n] + T2[n-1] with
// Tj[n] = sum_c wj_c * s_c[n] (linear channels only). One d-row per block,
// 2 warps (16 channels each) merged through one smem exchange; boundaries
// via shfl. 512 small blocks -> high resident parallelism for DRAM.
__global__ __launch_bounds__(64) void k3_build(
    const float* __restrict__ pw, const float* __restrict__ pb,
    const float* __restrict__ cw, const float* __restrict__ cb)
{
    __shared__ float sT[4][512];         // 8KB partials from half-1 warp
    const int hc   = threadIdx.x >> 5;   // channel half (warp id)
    const int lane = threadIdx.x & 31;
    const int d    = blockIdx.x;
    const float* prow = pw + (size_t)d * (CH * DIM);
    const size_t brow = (size_t)d * LDB;
    const int n0 = lane * 16;

    float T0[16], T1[16], T2[16], T3[16];
    #pragma unroll
    for (int j = 0; j < 16; j++) { T0[j] = 0.f; T1[j] = 0.f; T2[j] = 0.f; T3[j] = 0.f; }

    #pragma unroll 2
    for (int cc = 0; cc < 16; cc++) {
        const int c = hc * 16 + cc;
        const float4* sp = (const float4*)(prow + c * DIM + n0);
        float4 a0 = sp[0], a1 = sp[1], a2 = sp[2], a3 = sp[3];
        float s[16] = {a0.x,a0.y,a0.z,a0.w, a1.x,a1.y,a1.z,a1.w,
                       a2.x,a2.y,a2.z,a2.w, a3.x,a3.y,a3.z,a3.w};
        int cls = g_class[c];
        if (lane == 31) g_B[brow + 513 + c] = s[15];     // edge col (p==511)
        if (cls == 1) {
            float w0 = cw[c*3], w1 = cw[c*3+1], w2 = cw[c*3+2], bc = cb[c];
            #pragma unroll
            for (int j = 0; j < 16; j++) {
                T0[j] = fmaf(w0, s[j], T0[j]);
                T1[j] = fmaf(w1, s[j], T1[j]);
                T2[j] = fmaf(w2, s[j], T2[j]);
                T3[j] = fmaf(bc, s[j], T3[j]);
            }
        } else if (cls == 2) {
            size_t base = brow + 545 + (size_t)g_uidx[c] * 511 + n0;
            #pragma unroll
            for (int j = 0; j < 16; j++)
                if (n0 + j < 511) g_B[base + j] = s[j];  // scalar (base not 16B-aligned)
        }
    }

    if (hc == 1) {
        #pragma unroll
        for (int j = 0; j < 16; j++) {
            sT[0][n0 + j] = T0[j];
            sT[1][n0 + j] = T1[j];
            sT[2][n0 + j] = T2[j];
            sT[3][n0 + j] = T3[j];
        }
    }
    __syncthreads();
    if (hc == 0) {
        #pragma unroll
        for (int j = 0; j < 16; j++) {
            T0[j] += sT[0][n0 + j];
            T1[j] += sT[1][n0 + j];
            T2[j] += sT[2][n0 + j];
            T3[j] += sT[3][n0 + j];
        }
        float t0n = __shfl_down_sync(0xffffffffu, T0[0], 1);   // T0[n0+16]
        float t2p = __shfl_up_sync(0xffffffffu, T2[15], 1);    // T2[n0-1]
        float acc[16];
        #pragma unroll
        for (int j = 0; j < 16; j++) {
            int n = n0 + j;
            float t0 = (j < 15) ? T0[j + 1] : t0n;
            float t2 = (j > 0) ? T2[j - 1] : t2p;
            float v = 0.0f;
            if (n <= 509) v += t0;
            if (n <= 510) v += T1[j];
            if (n >= 1)   v += t2;
            acc[j] = v;
        }
        float4* dst = (float4*)&g_B[brow + n0];
        dst[0] = make_float4(acc[0],  acc[1],  acc[2],  acc[3]);
        dst[1] = make_float4(acc[4],  acc[5],  acc[6],  acc[7]);
        dst[2] = make_float4(acc[8],  acc[9],  acc[10], acc[11]);
        dst[3] = make_float4(acc[12], acc[13], acc[14], acc[15]);
        float tsum = 0.0f;
        #pragma unroll
        for (int j = 0; j < 16; j++)
            if (n0 + j <= 510) tsum += T3[j];
        #pragma unroll
        for (int off = 16; off > 0; off >>= 1)
            tsum += __shfl_xor_sync(0xffffffffu, tsum, off);
        if (lane == 0) g_B[brow + 512] = tsum + pb[d];   // const column
    }
}

// ---------- K3.5: transpose + hi/lo split B -> Bt[n][k] (grid-stride) -------
__global__ __launch_bounds__(256) void k35_convertB() {
    const int Ncols = g_N;
    const int nt32 = ((Ncols + 63) & ~63) >> 5;   // n-tiles of 32 (cover 64-wide k4 tiles)
    const int total = nt32 * 16;                  // 16 k-tiles of 32
    __shared__ float tile[32][33];
    int tx = threadIdx.x & 31, ty = threadIdx.x >> 5;   // ty 0..7
    for (int tl = blockIdx.x; tl < total; tl += gridDim.x) {
        int n0 = (tl >> 4) * 32;
        int k0 = (tl & 15) * 32;
        #pragma unroll
        for (int rr = 0; rr < 4; rr++) {
            int kk = ty + rr * 8;
            tile[kk][tx] = g_B[(size_t)(k0 + kk) * LDB + n0 + tx];
        }
        __syncthreads();
        #pragma unroll
        for (int rr = 0; rr < 4; rr++) {
            int nn = ty + rr * 8;
            float v = tile[tx][nn];
            __nv_bfloat16 hv = __float2bfloat16(v);
            float lv = v - __bfloat162float(hv);
            g_Bth[(size_t)(n0 + nn) * DIM + k0 + tx] = hv;
            g_Btl[(size_t)(n0 + nn) * DIM + k0 + tx] = __float2bfloat16(lv);
        }
        __syncthreads();
    }
}

// -------------------- coef(row, col) for the scoring epilogue ---------------
__device__ __forceinline__ float coef_fn(int row, int n, int Ncols,
                                         const float* __restrict__ cw,
                                         const float* __restrict__ cb)
{
    if (n >= Ncols) return 0.0f;
    if (n < 512)  return g_H[(size_t)row * DIM + n];
    if (n == 512) return 1.0f;
    const float* Hr = &g_H[(size_t)row * DIM];
    if (n < 545) {
        int c = n - 513;
        float v = fmaf(cw[c * 3], Hr[510],
                  fmaf(cw[c * 3 + 1], Hr[511],
                  fmaf(cw[c * 3 + 2], g_r0[row], cb[c])));
        return fmaxf(v, 0.0f);
    }
    int q = n - 545;
    int ui = q / 511;
    int p = q - ui * 511;                // p in [0, 510]
    int c = g_unc[ui];
    float xm1 = (p == 0) ? 0.0f : Hr[p - 1];
    float v = fmaf(cw[c * 3], xm1,
              fmaf(cw[c * 3 + 1], Hr[p],
              fmaf(cw[c * 3 + 2], Hr[p + 1], cb[c])));
    return fmaxf(v, 0.0f);
}

// ---------- K4: persistent tensor-core GEMM + fused scoring (grid-stride) ---
// 64(m) x 64(n) tiles, k-tile 16, 4-stage cp.async ring (48KB static smem),
// ldmatrix fragments, rows padded to 24 bf16 (48B stride, conflict-free).
// Stage layout (bf16 elements): AH 0 (64x24), AL 1536, BH 3072, BL 4608.
// m-tile fastest in the tile index: consecutive blocks share the B tile in L2.
#define K4_STRIDE 24
#define K4_STAGE  6144

__global__ __launch_bounds__(128) void k4_gemm(
    const float* __restrict__ cw, const float* __restrict__ cb,
    float* __restrict__ out)
{
    const int Ncols = g_N;
    const int ntn = (Ncols + 63) >> 6;
    const int total = ntn * 32;          // 32 m-tiles of 64

    __shared__ __align__(16) __nv_bfloat16 smem[4 * K4_STAGE];   // 49,152 B
    const unsigned sbase = (unsigned)__cvta_generic_to_shared(smem);

    const int tid  = threadIdx.x;
    const int lane = tid & 31;
    const int wn   = tid >> 5;           // 0..3 (n 16-offset)
    const int g = lane >> 2;             // 0..7
    const int q = lane & 3;              // 0..3

    // per-thread cp.async mapping (128 threads, 4 x 16B each)
    const int l_row  = tid >> 1;         // 0..63
    const int l_half = (tid & 1) * 8;    // 0 or 8

    // ldmatrix lane addressing (element offsets within a stage)
    const int a_r = lane & 15;                        // row within 16-row subtile
    const int a_c = (lane >> 4) << 3;                 // 0 or 8 (k-half)
    const int b_r = ((lane >> 4) << 3) + (lane & 7);  // row within 16-n slice
    const int b_c = ((lane >> 3) & 1) << 3;           // 0 or 8 (k-half)

    for (int tl = blockIdx.x; tl < total; tl += gridDim.x) {
        const int n0 = (tl >> 5) * 64;
        const int m0 = (tl & 31) * 64;

        float c_[4][2][4];
        #pragma unroll
        for (int s = 0; s < 4; s++)
            #pragma unroll
            for (int u = 0; u < 2; u++)
                #pragma unroll
                for (int e = 0; e < 4; e++) c_[s][u][e] = 0.0f;

        auto load_stage = [&](int st, int kc) {
            unsigned stb = sbase + (unsigned)(st * K4_STAGE) * 2;
            unsigned dA = stb + (unsigned)(l_row * K4_STRIDE + l_half) * 2;
            CP_ASYNC_16(dA,            g_Ah + (size_t)(m0 + l_row) * DIM + kc + l_half);
            CP_ASYNC_16(dA + 1536 * 2, g_Al + (size_t)(m0 + l_row) * DIM + kc + l_half);
            unsigned dB = stb + (unsigned)(3072 + l_row * K4_STRIDE + l_half) * 2;
            CP_ASYNC_16(dB,            g_Bth + (size_t)(n0 + l_row) * DIM + kc + l_half);
            CP_ASYNC_16(dB + 1536 * 2, g_Btl + (size_t)(n0 + l_row) * DIM + kc + l_half);
        };

        load_stage(0, 0);  CP_COMMIT();
        load_stage(1, 16); CP_COMMIT();
        load_stage(2, 32); CP_COMMIT();

        #pragma unroll 1
        for (int it = 0; it < 32; it++) {
            if (it < 30) { CP_WAIT2(); }
            else if (it == 30) { CP_WAIT1(); }
            else { CP_WAIT0(); }
            __syncthreads();
            if (it < 29) { load_stage((it + 3) & 3, (it + 3) * 16); CP_COMMIT(); }

            unsigned stb = sbase + (unsigned)((it & 3) * K4_STAGE) * 2;
            unsigned afh[4][4], afl[4][4], bh[4], bl[4];
            #pragma unroll
            for (int s = 0; s < 4; s++) {
                int r = s * 16 + a_r;
                unsigned aH = stb + (unsigned)(r * K4_STRIDE + a_c) * 2;
                LDSM_X4(afh[s][0], afh[s][1], afh[s][2], afh[s][3], aH);
                LDSM_X4(afl[s][0], afl[s][1], afl[s][2], afl[s][3], aH + 1536 * 2);
            }
            {
                int r = wn * 16 + b_r;
                unsigned aB = stb + (unsigned)(3072 + r * K4_STRIDE + b_c) * 2;
                LDSM_X4(bh[0], bh[1], bh[2], bh[3], aB);
                LDSM_X4(bl[0], bl[1], bl[2], bl[3], aB + 1536 * 2);
            }
            #pragma unroll
            for (int s = 0; s < 4; s++)
                #pragma unroll
                for (int u = 0; u < 2; u++) {
                    MMA_BF16(c_[s][u], afh[s], bh[2 * u], bh[2 * u + 1]);
                    MMA_BF16(c_[s][u], afh[s], bl[2 * u], bl[2 * u + 1]);
                    MMA_BF16(c_[s][u], afl[s], bh[2 * u], bh[2 * u + 1]);
                }
        }

        // epilogue: coef-weighted reduction, then width-4 shfl + atomicAdd
        #pragma unroll
        for (int s = 0; s < 4; s++) {
            int row0 = m0 + s * 16 + g;
            int row1 = row0 + 8;
            float rs0 = 0.0f, rs1 = 0.0f;
            #pragma unroll
            for (int u = 0; u < 2; u++) {
                int n = n0 + wn * 16 + u * 8 + 2 * q;
                float cf00 = coef_fn(row0, n,     Ncols, cw, cb);
                float cf01 = coef_fn(row0, n + 1, Ncols, cw, cb);
                float cf10 = coef_fn(row1, n,     Ncols, cw, cb);
                float cf11 = coef_fn(row1, n + 1, Ncols, cw, cb);
                rs0 = fmaf(c_[s][u][0], cf00, fmaf(c_[s][u][1], cf01, rs0));
                rs1 = fmaf(c_[s][u][2], cf10, fmaf(c_[s][u][3], cf11, rs1));
            }
            rs0 += __shfl_down_sync(0xffffffffu, rs0, 2, 4);
            rs0 += __shfl_down_sync(0xffffffffu, rs0, 1, 4);
            rs1 += __shfl_down_sync(0xffffffffu, rs1, 2, 4);
            rs1 += __shfl_down_sync(0xffffffffu, rs1, 1, 4);
            if (q == 0) {
                atomicAdd(&out[row0], rs0);
                atomicAdd(&out[row1], rs1);
            }
        }
        __syncthreads();   // smem stage buffers quiesce before next tile
    }
}

// ---------------------------------------------------------------------------
extern "C" void kernel_launch(void* const* d_in, const int* in_sizes, int n_in,
                              void* d_out, int out_size)
{
    const int*   h      = (const int*)  d_in[0];
    const int*   r      = (const int*)  d_in[1];
    const int*   t      = (const int*)  d_in[2];
    const float* ent    = (const float*)d_in[3];
    const float* rel    = (const float*)d_in[4];
    const float* conv_w = (const float*)d_in[5];
    const float* conv_b = (const float*)d_in[6];
    const float* proj_w = (const float*)d_in[7];
    const float* proj_b = (const float*)d_in[8];
    float* out = (float*)d_out;

    k0_init<<<8, 256>>>(out);
    k1_gather<<<BATCH, 128>>>(h, r, t, ent, rel);
    k2_classify<<<1, 32>>>(conv_w, conv_b);
    k3_build<<<512, 64>>>(proj_w, proj_b, conv_w, conv_b);
    k35_convertB<<<296, 256>>>();
    k4_gemm<<<296, 128>>>(conv_w, conv_b, out);
}

// round 11
// speedup vs baseline: 2.7181x; 1.0096x over previous
#include <cuda_runtime.h>
#include <cuda_bf16.h>

// ---------------------------------------------------------------------------
// ConvTransE scoring, algebraically reduced:
//   score[i] = e_t[i]^T (proj_w @ relu(conv(x_i)+b) + proj_b),  x_i = [h_e ; r_e]
// Linear/zero channels folded into an effective 512x512 matrix; the few
// "uncertain" channels + the p==511 edge go through exact-ReLU correction
// columns of one fused GEMM. Tensor cores via hi/lo bf16 split (3x mma.sync
// m16n8k16), ldmatrix fragments, 4-stage cp.async pipeline in STATIC smem.
// K3 fold is BRANCHLESS (per-channel effective weights) for load batching.
// ---------------------------------------------------------------------------

#define BATCH    2048
#define DIM      512
#define CH       32
#define LDB      16960          // >= 265*64, float4-aligned row stride of B
#define NMAXPAD  16960

__device__ __align__(16) float g_B[512 * LDB];       // built GEMM B matrix (fp32)
__device__ __align__(16) float g_H[BATCH * DIM];     // gathered h_e rows (fp32, coefs)
__device__ __align__(16) __nv_bfloat16 g_Ah[BATCH * DIM];   // A hi
__device__ __align__(16) __nv_bfloat16 g_Al[BATCH * DIM];   // A lo
__device__ __align__(16) __nv_bfloat16 g_Bth[NMAXPAD * DIM]; // B^T hi  [n][k]
__device__ __align__(16) __nv_bfloat16 g_Btl[NMAXPAD * DIM]; // B^T lo  [n][k]
__device__ float        g_r0[BATCH];               // rel[r[i]][0]
__device__ unsigned int g_xmax_bits;               // max |h_e| over gathered rows
__device__ float4       g_weff[CH];                // (w0,w1,w2,b) if linear else 0
__device__ int          g_class[CH];               // 0=zero 1=linear 2=uncertain
__device__ int          g_unc[CH];                 // compact list of uncertain channels
__device__ int          g_uidx[CH];                // channel -> index in g_unc
__device__ int          g_N;                       // runtime #columns = 545 + 511*U

#define MMA_BF16(C, A, B0, B1) \
    asm volatile("mma.sync.aligned.m16n8k16.row.col.f32.bf16.bf16.f32 " \
        "{%0,%1,%2,%3},{%4,%5,%6,%7},{%8,%9},{%0,%1,%2,%3};" \
        : "+f"(C[0]), "+f"(C[1]), "+f"(C[2]), "+f"(C[3]) \
        : "r"(A[0]), "r"(A[1]), "r"(A[2]), "r"(A[3]), "r"(B0), "r"(B1))

#define LDSM_X4(d0, d1, d2, d3, addr) \
    asm volatile("ldmatrix.sync.aligned.m8n8.x4.shared.b16 {%0,%1,%2,%3}, [%4];" \
        : "=r"(d0), "=r"(d1), "=r"(d2), "=r"(d3) : "r"(addr))

#define CP_ASYNC_16(dst, src) \
    asm volatile("cp.async.cg.shared.global [%0], [%1], 16;" :: "r"(dst), "l"(src))
#define CP_COMMIT() asm volatile("cp.async.commit_group;")
#define CP_WAIT2()  asm volatile("cp.async.wait_group 2;")
#define CP_WAIT1()  asm volatile("cp.async.wait_group 1;")
#define CP_WAIT0()  asm volatile("cp.async.wait_group 0;")

// -------------------- K0: init (zero scores only) ---------------------------
__global__ __launch_bounds__(256) void k0_init(float* __restrict__ out) {
    int id = blockIdx.x * blockDim.x + threadIdx.x;
    if (id < BATCH) out[id] = 0.0f;
    if (id == 0) g_xmax_bits = 0u;
}

// ------------------- K1: gather rows + max|h_e| + A hi/lo split -------------
__global__ __launch_bounds__(128) void k1_gather(
    const int* __restrict__ h, const int* __restrict__ r, const int* __restrict__ t,
    const float* __restrict__ ent, const float* __restrict__ rel)
{
    int i = blockIdx.x;
    int tid = threadIdx.x;               // 128 threads, one float4 each
    const float4* hs = (const float4*)(ent + (size_t)h[i] * DIM);
    const float4* ts = (const float4*)(ent + (size_t)t[i] * DIM);
    float4 hv = hs[tid];
    float4 tv = ts[tid];
    ((float4*)g_H)[i * 128 + tid] = hv;
    {
        float v[4] = {tv.x, tv.y, tv.z, tv.w};
        size_t base = (size_t)i * DIM + tid * 4;
        #pragma unroll
        for (int j = 0; j < 4; j++) {
            __nv_bfloat16 hi = __float2bfloat16(v[j]);
            __nv_bfloat16 lo = __float2bfloat16(v[j] - __bfloat162float(hi));
            g_Ah[base + j] = hi;
            g_Al[base + j] = lo;
        }
    }
    float m = fmaxf(fmaxf(fabsf(hv.x), fabsf(hv.y)), fmaxf(fabsf(hv.z), fabsf(hv.w)));
    #pragma unroll
    for (int off = 16; off > 0; off >>= 1)
        m = fmaxf(m, __shfl_xor_sync(0xffffffffu, m, off));
    __shared__ float wm[4];
    if ((tid & 31) == 0) wm[tid >> 5] = m;
    __syncthreads();
    if (tid == 0) {
        float mm = fmaxf(fmaxf(wm[0], wm[1]), fmaxf(wm[2], wm[3]));
        atomicMax(&g_xmax_bits, __float_as_uint(mm));
        g_r0[i] = rel[(size_t)r[i] * DIM];
    }
}

// ------------------------------------------- K2: per-channel classification
__global__ void k2_classify(const float* __restrict__ cw, const float* __restrict__ cb) {
    int c = threadIdx.x;                 // 32 threads (one full warp)
    float xmax = __uint_as_float(g_xmax_bits);
    float w0 = cw[c * 3 + 0], w1 = cw[c * 3 + 1], w2 = cw[c * 3 + 2];
    float bound = (fabsf(w0) + fabsf(w1) + fabsf(w2)) * xmax;
    float b = cb[c];
    int cls = (b >= bound) ? 1 : ((b <= -bound) ? 0 : 2);
    g_class[c] = cls;
    g_weff[c] = (cls == 1) ? make_float4(w0, w1, w2, b)
                           : make_float4(0.f, 0.f, 0.f, 0.f);
    unsigned m = __ballot_sync(0xffffffffu, cls == 2);
    if (cls == 2) {
        int idx = __popc(m & ((1u << c) - 1u));
        g_unc[idx] = c;
        g_uidx[c] = idx;
    }
    if (c == 0) g_N = 545 + 511 * __popc(m);
}

// ------------------------------------------- K3: fold conv+proj_w into B
// BRANCHLESS streaming register fold: acc[n] = T0[n+1] + T1[n] + T2[n-1],
// Tj[n] = sum_c weff_j[c] * s_c[n]. Zero-weight FMAs for non-linear channels
// are exact no-ops, so the hot loop has no data-dependent branches and ptxas
// can batch the streaming loads. Uncertain-channel scatter moved after the
// loop (reads are L1/L2-warm). One d-row per block, 2 warps of 16 channels.
__global__ __launch_bounds__(64) void k3_build(
    const float* __restrict__ pw, const float* __restrict__ pb,
    const float* __restrict__ cw, const float* __restrict__ cb)
{
    __shared__ float sT[4][512];         // 8KB partials from half-1 warp
    const int hc   = threadIdx.x >> 5;   // channel half (warp id)
    const int lane = threadIdx.x & 31;
    const int d    = blockIdx.x;
    const float* prow = pw + (size_t)d * (CH * DIM);
    const size_t brow = (size_t)d * LDB;
    const int n0 = lane * 16;

    float T0[16], T1[16], T2[16], T3[16];
    #pragma unroll
    for (int j = 0; j < 16; j++) { T0[j] = 0.f; T1[j] = 0.f; T2[j] = 0.f; T3[j] = 0.f; }

    #pragma unroll 2
    for (int cc = 0; cc < 16; cc++) {
        const int c = hc * 16 + cc;
        const float4* sp = (const float4*)(prow + c * DIM + n0);
        float4 a0 = sp[0], a1 = sp[1], a2 = sp[2], a3 = sp[3];
        float s[16] = {a0.x,a0.y,a0.z,a0.w, a1.x,a1.y,a1.z,a1.w,
                       a2.x,a2.y,a2.z,a2.w, a3.x,a3.y,a3.z,a3.w};
        float4 w = g_weff[c];
        if (lane == 31) g_B[brow + 513 + c] = s[15];     // edge col (p==511)
        #pragma unroll
        for (int j = 0; j < 16; j++) {
            T0[j] = fmaf(w.x, s[j], T0[j]);
            T1[j] = fmaf(w.y, s[j], T1[j]);
            T2[j] = fmaf(w.z, s[j], T2[j]);
            T3[j] = fmaf(w.w, s[j], T3[j]);
        }
    }

    if (hc == 1) {
        #pragma unroll
        for (int j = 0; j < 16; j++) {
            sT[0][n0 + j] = T0[j];
            sT[1][n0 + j] = T1[j];
            sT[2][n0 + j] = T2[j];
            sT[3][n0 + j] = T3[j];
        }
    }
    __syncthreads();
    if (hc == 0) {
        #pragma unroll
        for (int j = 0; j < 16; j++) {
            T0[j] += sT[0][n0 + j];
            T1[j] += sT[1][n0 + j];
            T2[j] += sT[2][n0 + j];
            T3[j] += sT[3][n0 + j];
        }
        float t0n = __shfl_down_sync(0xffffffffu, T0[0], 1);   // T0[n0+16]
        float t2p = __shfl_up_sync(0xffffffffu, T2[15], 1);    // T2[n0-1]
        float acc[16];
        #pragma unroll
        for (int j = 0; j < 16; j++) {
            int n = n0 + j;
            float t0 = (j < 15) ? T0[j + 1] : t0n;
            float t2 = (j > 0) ? T2[j - 1] : t2p;
            float v = 0.0f;
            if (n <= 509) v += t0;
            if (n <= 510) v += T1[j];
            if (n >= 1)   v += t2;
            acc[j] = v;
        }
        float4* dst = (float4*)&g_B[brow + n0];
        dst[0] = make_float4(acc[0],  acc[1],  acc[2],  acc[3]);
        dst[1] = make_float4(acc[4],  acc[5],  acc[6],  acc[7]);
        dst[2] = make_float4(acc[8],  acc[9],  acc[10], acc[11]);
        dst[3] = make_float4(acc[12], acc[13], acc[14], acc[15]);
        float tsum = 0.0f;
        #pragma unroll
        for (int j = 0; j < 16; j++)
            if (n0 + j <= 510) tsum += T3[j];
        #pragma unroll
        for (int off = 16; off > 0; off >>= 1)
            tsum += __shfl_xor_sync(0xffffffffu, tsum, off);
        if (lane == 0) g_B[brow + 512] = tsum + pb[d];   // const column
    }

    // uncertain-channel correction columns (data is L1/L2-warm from the fold)
    const int U = (g_N - 545) / 511;
    for (int ui = 0; ui < U; ui++) {
        const float* src = prow + g_unc[ui] * DIM;
        size_t base = brow + 545 + (size_t)ui * 511;
        for (int p = threadIdx.x; p < 511; p += 64)
            g_B[base + p] = src[p];
    }
}

// ---------- K3.5: transpose + hi/lo split B -> Bt[n][k] (grid-stride) -------
__global__ __launch_bounds__(256) void k35_convertB() {
    const int Ncols = g_N;
    const int nt32 = ((Ncols + 63) & ~63) >> 5;   // n-tiles of 32 (cover 64-wide k4 tiles)
    const int total = nt32 * 16;                  // 16 k-tiles of 32
    __shared__ float tile[32][33];
    int tx = threadIdx.x & 31, ty = threadIdx.x >> 5;   // ty 0..7
    for (int tl = blockIdx.x; tl < total; tl += gridDim.x) {
        int n0 = (tl >> 4) * 32;
        int k0 = (tl & 15) * 32;
        #pragma unroll
        for (int rr = 0; rr < 4; rr++) {
            int kk = ty + rr * 8;
            tile[kk][tx] = g_B[(size_t)(k0 + kk) * LDB + n0 + tx];
        }
        __syncthreads();
        #pragma unroll
        for (int rr = 0; rr < 4; rr++) {
            int nn = ty + rr * 8;
            float v = tile[tx][nn];
            __nv_bfloat16 hv = __float2bfloat16(v);
            float lv = v - __bfloat162float(hv);
            g_Bth[(size_t)(n0 + nn) * DIM + k0 + tx] = hv;
            g_Btl[(size_t)(n0 + nn) * DIM + k0 + tx] = __float2bfloat16(lv);
        }
        __syncthreads();
    }
}

// -------------------- coef(row, col) for the scoring epilogue ---------------
__device__ __forceinline__ float coef_fn(int row, int n, int Ncols,
                                         const float* __restrict__ cw,
                                         const float* __restrict__ cb)
{
    if (n >= Ncols) return 0.0f;
    if (n < 512)  return g_H[(size_t)row * DIM + n];
    if (n == 512) return 1.0f;
    const float* Hr = &g_H[(size_t)row * DIM];
    if (n < 545) {
        int c = n - 513;
        float v = fmaf(cw[c * 3], Hr[510],
                  fmaf(cw[c * 3 + 1], Hr[511],
                  fmaf(cw[c * 3 + 2], g_r0[row], cb[c])));
        return fmaxf(v, 0.0f);
    }
    int q = n - 545;
    int ui = q / 511;
    int p = q - ui * 511;                // p in [0, 510]
    int c = g_unc[ui];
    float xm1 = (p == 0) ? 0.0f : Hr[p - 1];
    float v = fmaf(cw[c * 3], xm1,
              fmaf(cw[c * 3 + 1], Hr[p],
              fmaf(cw[c * 3 + 2], Hr[p + 1], cb[c])));
    return fmaxf(v, 0.0f);
}

// ---------- K4: persistent tensor-core GEMM + fused scoring (grid-stride) ---
// 64(m) x 64(n) tiles, k-tile 16, 4-stage cp.async ring (48KB static smem),
// ldmatrix fragments, rows padded to 24 bf16 (48B stride, conflict-free).
// Stage layout (bf16 elements): AH 0 (64x24), AL 1536, BH 3072, BL 4608.
// m-tile fastest in the tile index: consecutive blocks share the B tile in L2.
#define K4_STRIDE 24
#define K4_STAGE  6144

__global__ __launch_bounds__(128) void k4_gemm(
    const float* __restrict__ cw, const float* __restrict__ cb,
    float* __restrict__ out)
{
    const int Ncols = g_N;
    const int ntn = (Ncols + 63) >> 6;
    const int total = ntn * 32;          // 32 m-tiles of 64

    __shared__ __align__(16) __nv_bfloat16 smem[4 * K4_STAGE];   // 49,152 B
    const unsigned sbase = (unsigned)__cvta_generic_to_shared(smem);

    const int tid  = threadIdx.x;
    const int lane = tid & 31;
    const int wn   = tid >> 5;           // 0..3 (n 16-offset)
    const int g = lane >> 2;             // 0..7
    const int q = lane & 3;              // 0..3

    // per-thread cp.async mapping (128 threads, 4 x 16B each)
    const int l_row  = tid >> 1;         // 0..63
    const int l_half = (tid & 1) * 8;    // 0 or 8

    // ldmatrix lane addressing (element offsets within a stage)
    const int a_r = lane & 15;                        // row within 16-row subtile
    const int a_c = (lane >> 4) << 3;                 // 0 or 8 (k-half)
    const int b_r = ((lane >> 4) << 3) + (lane & 7);  // row within 16-n slice
    const int b_c = ((lane >> 3) & 1) << 3;           // 0 or 8 (k-half)

    for (int tl = blockIdx.x; tl < total; tl += gridDim.x) {
        const int n0 = (tl >> 5) * 64;
        const int m0 = (tl & 31) * 64;

        float c_[4][2][4];
        #pragma unroll
        for (int s = 0; s < 4; s++)
            #pragma unroll
            for (int u = 0; u < 2; u++)
                #pragma unroll
                for (int e = 0; e < 4; e++) c_[s][u][e] = 0.0f;

        auto load_stage = [&](int st, int kc) {
            unsigned stb = sbase + (unsigned)(st * K4_STAGE) * 2;
            unsigned dA = stb + (unsigned)(l_row * K4_STRIDE + l_half) * 2;
            CP_ASYNC_16(dA,            g_Ah + (size_t)(m0 + l_row) * DIM + kc + l_half);
            CP_ASYNC_16(dA + 1536 * 2, g_Al + (size_t)(m0 + l_row) * DIM + kc + l_half);
            unsigned dB = stb + (unsigned)(3072 + l_row * K4_STRIDE + l_half) * 2;
            CP_ASYNC_16(dB,            g_Bth + (size_t)(n0 + l_row) * DIM + kc + l_half);
            CP_ASYNC_16(dB + 1536 * 2, g_Btl + (size_t)(n0 + l_row) * DIM + kc + l_half);
        };

        load_stage(0, 0);  CP_COMMIT();
        load_stage(1, 16); CP_COMMIT();
        load_stage(2, 32); CP_COMMIT();

        #pragma unroll 1
        for (int it = 0; it < 32; it++) {
            if (it < 30) { CP_WAIT2(); }
            else if (it == 30) { CP_WAIT1(); }
            else { CP_WAIT0(); }
            __syncthreads();
            if (it < 29) { load_stage((it + 3) & 3, (it + 3) * 16); CP_COMMIT(); }

            unsigned stb = sbase + (unsigned)((it & 3) * K4_STAGE) * 2;
            unsigned afh[4][4], afl[4][4], bh[4], bl[4];
            #pragma unroll
            for (int s = 0; s < 4; s++) {
                int r = s * 16 + a_r;
                unsigned aH = stb + (unsigned)(r * K4_STRIDE + a_c) * 2;
                LDSM_X4(afh[s][0], afh[s][1], afh[s][2], afh[s][3], aH);
                LDSM_X4(afl[s][0], afl[s][1], afl[s][2], afl[s][3], aH + 1536 * 2);
            }
            {
                int r = wn * 16 + b_r;
                unsigned aB = stb + (unsigned)(3072 + r * K4_STRIDE + b_c) * 2;
                LDSM_X4(bh[0], bh[1], bh[2], bh[3], aB);
                LDSM_X4(bl[0], bl[1], bl[2], bl[3], aB + 1536 * 2);
            }
            #pragma unroll
            for (int s = 0; s < 4; s++)
                #pragma unroll
                for (int u = 0; u < 2; u++) {
                    MMA_BF16(c_[s][u], afh[s], bh[2 * u], bh[2 * u + 1]);
                    MMA_BF16(c_[s][u], afh[s], bl[2 * u], bl[2 * u + 1]);
                    MMA_BF16(c_[s][u], afl[s], bh[2 * u], bh[2 * u + 1]);
                }
        }

        // epilogue: coef-weighted reduction, then width-4 shfl + atomicAdd
        #pragma unroll
        for (int s = 0; s < 4; s++) {
            int row0 = m0 + s * 16 + g;
            int row1 = row0 + 8;
            float rs0 = 0.0f, rs1 = 0.0f;
            #pragma unroll
            for (int u = 0; u < 2; u++) {
                int n = n0 + wn * 16 + u * 8 + 2 * q;
                float cf00 = coef_fn(row0, n,     Ncols, cw, cb);
                float cf01 = coef_fn(row0, n + 1, Ncols, cw, cb);
                float cf10 = coef_fn(row1, n,     Ncols, cw, cb);
                float cf11 = coef_fn(row1, n + 1, Ncols, cw, cb);
                rs0 = fmaf(c_[s][u][0], cf00, fmaf(c_[s][u][1], cf01, rs0));
                rs1 = fmaf(c_[s][u][2], cf10, fmaf(c_[s][u][3], cf11, rs1));
            }
            rs0 += __shfl_down_sync(0xffffffffu, rs0, 2, 4);
            rs0 += __shfl_down_sync(0xffffffffu, rs0, 1, 4);
            rs1 += __shfl_down_sync(0xffffffffu, rs1, 2, 4);
            rs1 += __shfl_down_sync(0xffffffffu, rs1, 1, 4);
            if (q == 0) {
                atomicAdd(&out[row0], rs0);
                atomicAdd(&out[row1], rs1);
            }
        }
        __syncthreads();   // smem stage buffers quiesce before next tile
    }
}

// ---------------------------------------------------------------------------
extern "C" void kernel_launch(void* const* d_in, const int* in_sizes, int n_in,
                              void* d_out, int out_size)
{
    const int*   h      = (const int*)  d_in[0];
    const int*   r      = (const int*)  d_in[1];
    const int*   t      = (const int*)  d_in[2];
    const float* ent    = (const float*)d_in[3];
    const float* rel    = (const float*)d_in[4];
    const float* conv_w = (const float*)d_in[5];
    const float* conv_b = (const float*)d_in[6];
    const float* proj_w = (const float*)d_in[7];
    const float* proj_b = (const float*)d_in[8];
    float* out = (float*)d_out;

    k0_init<<<8, 256>>>(out);
    k1_gather<<<BATCH, 128>>>(h, r, t, ent, rel);
    k2_classify<<<1, 32>>>(conv_w, conv_b);
    k3_build<<<512, 64>>>(proj_w, proj_b, conv_w, conv_b);
    k35_convertB<<<296, 256>>>();
    k4_gemm<<<296, 128>>>(conv_w, conv_b, out);
}